// round 1
// baseline (speedup 1.0000x reference)
#include <cuda_runtime.h>
#include <cuda_bf16.h>
#include <math.h>

// Problem constants (fixed by dataset)
#define MAXN 50000
#define MAXE 400000

// ---------------- scratch (device globals; no allocation allowed) ----------------
__device__ float g_hn[MAXN * 128];
__device__ float g_P1[MAXN * 128];
__device__ float g_P2[MAXN * 128];
__device__ float g_Q1[MAXN * 128];
__device__ float g_Q2[MAXN * 128];
__device__ float g_ow[(size_t)MAXE * 32];
__device__ float g_w1[(size_t)MAXE * 32];
__device__ float g_w2[(size_t)MAXE * 32];
__device__ float g_logits[MAXE];
__device__ float g_hagg[(size_t)MAXN * 160];
__device__ float g_Acat[(size_t)MAXN * 288];
__device__ int   g_rowstart[MAXN + 1];

// ---------------- K0: segment boundaries via binary search (dst sorted) ----------
__global__ void rowstart_kernel(const int* __restrict__ dst, int E, int Nn) {
    int n = blockIdx.x * blockDim.x + threadIdx.x;
    if (n > Nn) return;
    int lo = 0, hi = E;
    while (lo < hi) {
        int mid = (lo + hi) >> 1;
        if (dst[mid] < n) lo = mid + 1; else hi = mid;
    }
    g_rowstart[n] = lo;
}

// ---------------- generic node GEMM: C[M,128] = act(A[M,K] @ B[K,128] + bias) ----
// blockDim = 256, tile 64 rows x 128 cols, KC = 32
__global__ void gemm128(const float* __restrict__ A, const float* __restrict__ B,
                        const float* __restrict__ bias, float* __restrict__ C,
                        int M, int K) {
    __shared__ float As[64][33];
    __shared__ float Bs[32][128];
    int tid  = threadIdx.x;
    int row0 = blockIdx.x * 64;
    int col  = (tid & 31) * 4;
    int rgrp = tid >> 5;   // 0..7, uniform per warp
    float acc[8][4];
#pragma unroll
    for (int i = 0; i < 8; i++)
#pragma unroll
        for (int c = 0; c < 4; c++) acc[i][c] = 0.f;

    for (int kc = 0; kc < K; kc += 32) {
#pragma unroll
        for (int i = 0; i < 8; i++) {
            int e = tid + 256 * i;       // 0..2047
            int r = e >> 5, k = e & 31;
            int gr = row0 + r;
            As[r][k] = (gr < M) ? A[(size_t)gr * K + kc + k] : 0.f;
        }
#pragma unroll
        for (int i = 0; i < 16; i++) {
            int e = tid + 256 * i;       // 0..4095
            int kk = e >> 7, c = e & 127;
            Bs[kk][c] = B[(size_t)(kc + kk) * 128 + c];
        }
        __syncthreads();
#pragma unroll
        for (int k = 0; k < 32; k++) {
            float4 b = *(const float4*)&Bs[k][col];
#pragma unroll
            for (int i = 0; i < 8; i++) {
                float a = As[rgrp + 8 * i][k];
                acc[i][0] = fmaf(a, b.x, acc[i][0]);
                acc[i][1] = fmaf(a, b.y, acc[i][1]);
                acc[i][2] = fmaf(a, b.z, acc[i][2]);
                acc[i][3] = fmaf(a, b.w, acc[i][3]);
            }
        }
        __syncthreads();
    }
#pragma unroll
    for (int i = 0; i < 8; i++) {
        int gr = row0 + rgrp + 8 * i;
        if (gr < M) {
#pragma unroll
            for (int c = 0; c < 4; c++) {
                float v = acc[i][c];
                if (bias) v += bias[col + c];
                C[(size_t)gr * 128 + col + c] = v;
            }
        }
    }
}

// ---------------- K2: ow = w@W_ee ; s = lrelu(ow)@W_sf ; w1 = s*ow ---------------
// warp per edge, B columns cached in registers
__global__ void edge_embed_kernel(const float* __restrict__ w,
                                  const float* __restrict__ Wee,
                                  const float* __restrict__ Wsf, int E) {
    __shared__ float sWee[1024];
    __shared__ float sWsf[32];
    int tid = threadIdx.x;  // 256
    for (int i = tid; i < 1024; i += 256) sWee[i] = Wee[i];
    if (tid < 32) sWsf[tid] = Wsf[tid];
    __syncthreads();
    int lane = tid & 31;
    float Bcol[32];
#pragma unroll
    for (int k = 0; k < 32; k++) Bcol[k] = sWee[k * 32 + lane];
    float sfj = sWsf[lane];
    int warp   = (blockIdx.x * blockDim.x + tid) >> 5;
    int nwarps = (gridDim.x * blockDim.x) >> 5;
    for (int e = warp; e < E; e += nwarps) {
        float wv = w[(size_t)e * 32 + lane];
        float o = 0.f;
#pragma unroll
        for (int k = 0; k < 32; k++)
            o = fmaf(__shfl_sync(0xffffffffu, wv, k), Bcol[k], o);
        float l = o > 0.f ? o : 0.1f * o;
        float sv = l * sfj;
#pragma unroll
        for (int off = 16; off; off >>= 1) sv += __shfl_xor_sync(0xffffffffu, sv, off);
        g_ow[(size_t)e * 32 + lane] = o;
        g_w1[(size_t)e * 32 + lane] = sv * o;
    }
}

// ---------------- K4: sat output + z2/att/logits/w2 per edge ---------------------
// z2 = P1[src] + P2[dst] + b + w1@W3 ; att = lrelu(z2)@W_attn ; w2 = att*w1
__global__ void edge_fuse_kernel(const int* __restrict__ src, const int* __restrict__ dst,
                                 const float* __restrict__ Wif3,  // rows 256..287 of W_inter_fuse (32x128)
                                 const float* __restrict__ bif,
                                 const float* __restrict__ Wattn,
                                 float* __restrict__ sat_out, int E) {
    __shared__ float sW3[32 * 128];
    __shared__ float sWa[128];
    __shared__ float sb[128];
    __shared__ float sw1[32];
    __shared__ float red[4];
    __shared__ float satt;
    int tid = threadIdx.x;  // 128
    for (int i = tid; i < 32 * 128; i += 128) sW3[i] = Wif3[i];
    sWa[tid] = Wattn[tid];
    sb[tid]  = bif[tid];
    __syncthreads();
    for (int e = blockIdx.x; e < E; e += gridDim.x) {
        int s = src[e], d = dst[e];
        float hs = g_hn[(size_t)s * 128 + tid];
        float hd = g_hn[(size_t)d * 128 + tid];
        if (tid < 32) sw1[tid] = g_w1[(size_t)e * 32 + tid];
        __syncthreads();
        size_t so = (size_t)e * 288;
        sat_out[so + tid] = hs;
        sat_out[so + 128 + tid] = hd;
        if (tid < 32) sat_out[so + 256 + tid] = sw1[tid];
        float z = g_P1[(size_t)s * 128 + tid] + g_P2[(size_t)d * 128 + tid] + sb[tid];
#pragma unroll
        for (int k = 0; k < 32; k++) z = fmaf(sw1[k], sW3[k * 128 + tid], z);
        float inw = z > 0.f ? z : 0.1f * z;
        float v = inw * sWa[tid];
#pragma unroll
        for (int o = 16; o; o >>= 1) v += __shfl_xor_sync(0xffffffffu, v, o);
        if ((tid & 31) == 0) red[tid >> 5] = v;
        __syncthreads();
        if (tid == 0) {
            float att = red[0] + red[1] + red[2] + red[3];
            satt = att;
            g_logits[e] = att;
        }
        __syncthreads();
        float att = satt;
        if (tid < 32) g_w2[(size_t)e * 32 + tid] = att * sw1[tid];
        __syncthreads();
    }
}

// ---------------- K5/K6: segment softmax + weighted aggregate (warp per node) ----
__global__ void segment_kernel(const int* __restrict__ src, int Nn) {
    int warp = (blockIdx.x * blockDim.x + threadIdx.x) >> 5;
    int lane = threadIdx.x & 31;
    if (warp >= Nn) return;
    int s0 = g_rowstart[warp], s1 = g_rowstart[warp + 1];
    float acc[5] = {0.f, 0.f, 0.f, 0.f, 0.f};
    if (s1 > s0) {
        float m = -INFINITY;
        for (int e = s0 + lane; e < s1; e += 32) m = fmaxf(m, g_logits[e]);
#pragma unroll
        for (int o = 16; o; o >>= 1) m = fmaxf(m, __shfl_xor_sync(0xffffffffu, m, o));
        float den = 0.f;
        for (int e = s0 + lane; e < s1; e += 32) den += expf(g_logits[e] - m);
#pragma unroll
        for (int o = 16; o; o >>= 1) den += __shfl_xor_sync(0xffffffffu, den, o);
        float inv = 1.0f / den;
        for (int e = s0; e < s1; e++) {
            float alpha = expf(g_logits[e] - m) * inv;
            int sidx = src[e];
#pragma unroll
            for (int i = 0; i < 4; i++)
                acc[i] = fmaf(alpha, g_hn[(size_t)sidx * 128 + lane + 32 * i], acc[i]);
            acc[4] = fmaf(alpha, g_w2[(size_t)e * 32 + lane], acc[4]);
        }
    }
#pragma unroll
    for (int i = 0; i < 4; i++) g_hagg[(size_t)warp * 160 + lane + 32 * i] = acc[i];
    g_hagg[(size_t)warp * 160 + 128 + lane] = acc[4];
}

// ---------------- build Acat = [hagg(160), hn(128)] ------------------------------
__global__ void build_acat(int Nn) {
    int r = blockIdx.x;
    int c = threadIdx.x;  // 288
    if (r >= Nn) return;
    float v = (c < 160) ? g_hagg[(size_t)r * 160 + c] : g_hn[(size_t)r * 128 + (c - 160)];
    g_Acat[(size_t)r * 288 + c] = v;
}

// ---------------- fixup: hnew = hn where deg == 0 --------------------------------
__global__ void hnew_fixup(float* __restrict__ hnew, int Nn) {
    int idx = blockIdx.x * blockDim.x + threadIdx.x;
    if (idx >= Nn * 128) return;
    int r = idx >> 7;
    if (g_rowstart[r + 1] == g_rowstart[r]) hnew[idx] = g_hn[idx];
}

// ---------------- K9: wout = Q1[src] + Q2[dst] + [wbn,ow]@W_ag[256:320] ----------
__global__ void edge_out_kernel(const int* __restrict__ src, const int* __restrict__ dst,
                                const float* __restrict__ Wag3,  // rows 256..319 (64x128)
                                const float* __restrict__ gamma, const float* __restrict__ beta,
                                const float* __restrict__ mean,  const float* __restrict__ var,
                                float* __restrict__ wout, int E) {
    __shared__ float sW[64 * 128];
    __shared__ float sv[64];
    __shared__ float sbn[128];
    int tid = threadIdx.x;  // 128
    for (int i = tid; i < 64 * 128; i += 128) sW[i] = Wag3[i];
    if (tid < 32) {
        sbn[tid]       = gamma[tid];
        sbn[32 + tid]  = beta[tid];
        sbn[64 + tid]  = mean[tid];
        sbn[96 + tid]  = rsqrtf(var[tid] + 1e-5f);
    }
    __syncthreads();
    for (int e = blockIdx.x; e < E; e += gridDim.x) {
        int s = src[e], d = dst[e];
        if (tid < 32) {
            float wv = g_w2[(size_t)e * 32 + tid];
            sv[tid]      = (wv - sbn[64 + tid]) * sbn[96 + tid] * sbn[tid] + sbn[32 + tid];
            sv[32 + tid] = g_ow[(size_t)e * 32 + tid];
        }
        __syncthreads();
        float acc = g_Q1[(size_t)s * 128 + tid] + g_Q2[(size_t)d * 128 + tid];
#pragma unroll
        for (int k = 0; k < 64; k++) acc = fmaf(sv[k], sW[k * 128 + tid], acc);
        wout[(size_t)e * 128 + tid] = acc;
        __syncthreads();
    }
}

// ---------------- launch ----------------------------------------------------------
extern "C" void kernel_launch(void* const* d_in, const int* in_sizes, int n_in,
                              void* d_out, int out_size) {
    const float* h        = (const float*)d_in[0];
    const float* w        = (const float*)d_in[1];
    const int*   src      = (const int*)d_in[2];
    const int*   dst      = (const int*)d_in[3];
    const float* W_en     = (const float*)d_in[4];   // 128x128
    const float* W_attn   = (const float*)d_in[5];   // 128x1
    const float* W_if     = (const float*)d_in[6];   // 288x128
    const float* b_if     = (const float*)d_in[7];   // 128
    const float* W_ee     = (const float*)d_in[8];   // 32x32
    const float* W_sf     = (const float*)d_in[9];   // 32x1
    const float* W_conc   = (const float*)d_in[10];  // 288x128
    const float* b_conc   = (const float*)d_in[11];  // 128
    const float* bn_gamma = (const float*)d_in[12];
    const float* bn_beta  = (const float*)d_in[13];
    const float* bn_mean  = (const float*)d_in[14];
    const float* bn_var   = (const float*)d_in[15];
    const float* W_ag     = (const float*)d_in[16];  // 320x128

    int Nn = in_sizes[0] / 128;
    int E  = in_sizes[2];

    float* out_hnew = (float*)d_out;                          // N*128
    float* out_wout = out_hnew + (size_t)Nn * 128;            // E*128
    float* out_sat  = out_wout + (size_t)E * 128;             // E*288

    // device-global scratch addresses (resolved at compile time inside kernels;
    // host needs them only for gemm128 arguments)
    float *hn_p, *P1_p, *P2_p, *Q1_p, *Q2_p, *Acat_p;
    cudaGetSymbolAddress((void**)&hn_p,   g_hn);
    cudaGetSymbolAddress((void**)&P1_p,   g_P1);
    cudaGetSymbolAddress((void**)&P2_p,   g_P2);
    cudaGetSymbolAddress((void**)&Q1_p,   g_Q1);
    cudaGetSymbolAddress((void**)&Q2_p,   g_Q2);
    cudaGetSymbolAddress((void**)&Acat_p, g_Acat);

    int gemm_blocks = (Nn + 63) / 64;

    // K0: segment boundaries
    rowstart_kernel<<<(Nn + 256) / 256, 256>>>(dst, E, Nn);
    // K1: hn = h @ W_embed_node
    gemm128<<<gemm_blocks, 256>>>(h, W_en, nullptr, hn_p, Nn, 128);
    // K2: ow / w1
    edge_embed_kernel<<<1024, 256>>>(w, W_ee, W_sf, E);
    // K3: P1, P2 (node-level halves of W_inter_fuse)
    gemm128<<<gemm_blocks, 256>>>(hn_p, W_if,              nullptr, P1_p, Nn, 128);
    gemm128<<<gemm_blocks, 256>>>(hn_p, W_if + 128 * 128,  nullptr, P2_p, Nn, 128);
    // K4: sat + logits + w2
    edge_fuse_kernel<<<8192, 128>>>(src, dst, W_if + 256 * 128, b_if, W_attn, out_sat, E);
    // K5/K6: segment softmax + aggregate
    segment_kernel<<<(Nn + 7) / 8, 256>>>(src, Nn);
    // K7: hnew = [hagg, hn] @ W_conc + b ; where(deg>0)
    build_acat<<<Nn, 288>>>(Nn);
    gemm128<<<gemm_blocks, 256>>>(Acat_p, W_conc, b_conc, out_hnew, Nn, 288);
    hnew_fixup<<<(Nn * 128 + 255) / 256, 256>>>(out_hnew, Nn);
    // K8: Q1, Q2 (node-level halves of W_aggre)
    gemm128<<<gemm_blocks, 256>>>(out_hnew, W_ag,             nullptr, Q1_p, Nn, 128);
    gemm128<<<gemm_blocks, 256>>>(out_hnew, W_ag + 128 * 128, nullptr, Q2_p, Nn, 128);
    // K9: wout
    edge_out_kernel<<<8192, 128>>>(src, dst, W_ag + 256 * 128,
                                   bn_gamma, bn_beta, bn_mean, bn_var, out_wout, E);
}

// round 2
// speedup vs baseline: 1.4702x; 1.4702x over previous
#include <cuda_runtime.h>
#include <cuda_bf16.h>
#include <math.h>

#define MAXN 50000
#define MAXE 400000

// ---------------- scratch (device globals) ----------------
__device__ float g_hn[MAXN * 128];
__device__ float g_P1[MAXN * 128];
__device__ float g_P2[MAXN * 128];
__device__ float g_Q1[MAXN * 128];
__device__ float g_Q2[MAXN * 128];
__device__ float g_ow[(size_t)MAXE * 32];
__device__ float g_w1[(size_t)MAXE * 32];
__device__ float g_w2[(size_t)MAXE * 32];
__device__ float g_logits[MAXE];
__device__ float g_Acat[(size_t)MAXN * 288];
__device__ int   g_rowstart[MAXN + 1];
__device__ float g_Wmod[64 * 128];
__device__ float g_cvec[128];

// ---------------- K0: segment boundaries (dst sorted) ----------------
__global__ void rowstart_kernel(const int* __restrict__ dst, int E, int Nn) {
    int n = blockIdx.x * blockDim.x + threadIdx.x;
    if (n > Nn) return;
    int lo = 0, hi = E;
    while (lo < hi) {
        int mid = (lo + hi) >> 1;
        if (dst[mid] < n) lo = mid + 1; else hi = mid;
    }
    g_rowstart[n] = lo;
}

// ---------------- gemm_v2: C[M,128] = A[M,K] @ B[K,128] (+bias) --------------
// 256 threads, tile 128x128, 8x8 per thread, As transposed for float4 LDS.
__global__ __launch_bounds__(256, 2)
void gemm_v2(const float* __restrict__ A, const float* __restrict__ B,
             const float* __restrict__ bias, float* __restrict__ C,
             int M, int K) {
    __shared__ float As[32][132];   // [k][r]
    __shared__ float Bs[32][132];   // [k][c]
    int tid = threadIdx.x;
    int tx = tid & 15;          // 16 col groups
    int ty = tid >> 4;          // 16 row groups
    int row0 = blockIdx.x * 128;

    float acc[2][4][2][4];
#pragma unroll
    for (int a = 0; a < 2; a++)
#pragma unroll
        for (int b = 0; b < 4; b++)
#pragma unroll
            for (int c = 0; c < 2; c++)
#pragma unroll
                for (int d = 0; d < 4; d++) acc[a][b][c][d] = 0.f;

    for (int kc = 0; kc < K; kc += 32) {
        // A tile: 128 rows x 32 k, stored transposed
#pragma unroll
        for (int i = 0; i < 4; i++) {
            int e = tid + 256 * i;           // 0..1023
            int r = e >> 3;
            int kg = e & 7;
            float4 v = make_float4(0.f, 0.f, 0.f, 0.f);
            if (row0 + r < M)
                v = *(const float4*)&A[(size_t)(row0 + r) * K + kc + kg * 4];
            As[kg * 4 + 0][r] = v.x;
            As[kg * 4 + 1][r] = v.y;
            As[kg * 4 + 2][r] = v.z;
            As[kg * 4 + 3][r] = v.w;
        }
        // B tile: 32 k x 128 cols
#pragma unroll
        for (int i = 0; i < 4; i++) {
            int e = tid + 256 * i;           // 0..1023
            int k = e >> 5;
            int cg = e & 31;
            *(float4*)&Bs[k][cg * 4] = *(const float4*)&B[(size_t)(kc + k) * 128 + cg * 4];
        }
        __syncthreads();
#pragma unroll
        for (int k = 0; k < 32; k++) {
            float4 a0 = *(const float4*)&As[k][ty * 4];
            float4 a1 = *(const float4*)&As[k][64 + ty * 4];
            float4 b0 = *(const float4*)&Bs[k][tx * 4];
            float4 b1 = *(const float4*)&Bs[k][64 + tx * 4];
            float av[2][4] = {{a0.x, a0.y, a0.z, a0.w}, {a1.x, a1.y, a1.z, a1.w}};
            float bv[2][4] = {{b0.x, b0.y, b0.z, b0.w}, {b1.x, b1.y, b1.z, b1.w}};
#pragma unroll
            for (int mi = 0; mi < 2; mi++)
#pragma unroll
                for (int j = 0; j < 4; j++)
#pragma unroll
                    for (int ni = 0; ni < 2; ni++)
#pragma unroll
                        for (int c = 0; c < 4; c++)
                            acc[mi][j][ni][c] = fmaf(av[mi][j], bv[ni][c], acc[mi][j][ni][c]);
        }
        __syncthreads();
    }
    // epilogue
    float4 bs0 = make_float4(0.f, 0.f, 0.f, 0.f), bs1 = bs0;
    if (bias) {
        bs0 = *(const float4*)&bias[tx * 4];
        bs1 = *(const float4*)&bias[64 + tx * 4];
    }
#pragma unroll
    for (int mi = 0; mi < 2; mi++)
#pragma unroll
        for (int j = 0; j < 4; j++) {
            int row = row0 + mi * 64 + ty * 4 + j;
            if (row < M) {
                float4 o0 = make_float4(acc[mi][j][0][0] + bs0.x, acc[mi][j][0][1] + bs0.y,
                                        acc[mi][j][0][2] + bs0.z, acc[mi][j][0][3] + bs0.w);
                float4 o1 = make_float4(acc[mi][j][1][0] + bs1.x, acc[mi][j][1][1] + bs1.y,
                                        acc[mi][j][1][2] + bs1.z, acc[mi][j][1][3] + bs1.w);
                *(float4*)&C[(size_t)row * 128 + tx * 4] = o0;
                *(float4*)&C[(size_t)row * 128 + 64 + tx * 4] = o1;
            }
        }
}

// ---------------- K2: ow = w@W_ee ; s = lrelu(ow)@W_sf ; w1 = s*ow -----------
__global__ void edge_embed_kernel(const float* __restrict__ w,
                                  const float* __restrict__ Wee,
                                  const float* __restrict__ Wsf, int E) {
    __shared__ float sWee[1024];
    __shared__ float sWsf[32];
    int tid = threadIdx.x;  // 256
    for (int i = tid; i < 1024; i += 256) sWee[i] = Wee[i];
    if (tid < 32) sWsf[tid] = Wsf[tid];
    __syncthreads();
    int lane = tid & 31;
    float Bcol[32];
#pragma unroll
    for (int k = 0; k < 32; k++) Bcol[k] = sWee[k * 32 + lane];
    float sfj = sWsf[lane];
    int warp   = (blockIdx.x * blockDim.x + tid) >> 5;
    int nwarps = (gridDim.x * blockDim.x) >> 5;
    for (int e = warp; e < E; e += nwarps) {
        float wv = w[(size_t)e * 32 + lane];
        float o = 0.f;
#pragma unroll
        for (int k = 0; k < 32; k++)
            o = fmaf(__shfl_sync(0xffffffffu, wv, k), Bcol[k], o);
        float l = o > 0.f ? o : 0.1f * o;
        float sv = l * sfj;
#pragma unroll
        for (int off = 16; off; off >>= 1) sv += __shfl_xor_sync(0xffffffffu, sv, off);
        g_ow[(size_t)e * 32 + lane] = o;
        g_w1[(size_t)e * 32 + lane] = sv * o;
    }
}

// ---------------- K4: per-edge fuse. Thread owns one output column. ----------
// 128 threads, 4 edges per iteration, W3 column in registers.
__global__ __launch_bounds__(128)
void edge_fuse_v2(const int* __restrict__ src, const int* __restrict__ dst,
                  const float* __restrict__ Wif3, const float* __restrict__ bif,
                  const float* __restrict__ Wattn,
                  float* __restrict__ sat_out, int E) {
    int tid = threadIdx.x;
    float W3c[32];
#pragma unroll
    for (int k = 0; k < 32; k++) W3c[k] = Wif3[k * 128 + tid];
    float wa = Wattn[tid];
    float bb = bif[tid];
    __shared__ float sw1t[32 * 4];  // [k][m]
    __shared__ int   sidx[8];       // {src,dst} x 4
    __shared__ float red[4][4];     // [warp][m]
    __shared__ float satt[4];
    int warp = tid >> 5, lane = tid & 31;

    for (int e0 = blockIdx.x * 4; e0 < E; e0 += gridDim.x * 4) {
        int nE = E - e0; if (nE > 4) nE = 4;
        if (tid < 8) {
            int m = tid >> 1;
            int ee = e0 + (m < nE ? m : nE - 1);
            sidx[tid] = (tid & 1) ? dst[ee] : src[ee];
        }
        {
            int m = tid >> 5, k = tid & 31;
            int mm = m < nE ? m : nE - 1;
            sw1t[k * 4 + m] = g_w1[(size_t)(e0 + mm) * 32 + k];
        }
        __syncthreads();

        int s[4], d[4];
        float z[4];
#pragma unroll
        for (int m = 0; m < 4; m++) {
            s[m] = sidx[m * 2];
            d[m] = sidx[m * 2 + 1];
            z[m] = g_P1[(size_t)s[m] * 128 + tid] + g_P2[(size_t)d[m] * 128 + tid] + bb;
        }
        // sat outputs (hs, hd, w1)
#pragma unroll
        for (int m = 0; m < 4; m++) {
            if (m < nE) {
                size_t so = (size_t)(e0 + m) * 288;
                sat_out[so + tid]       = g_hn[(size_t)s[m] * 128 + tid];
                sat_out[so + 128 + tid] = g_hn[(size_t)d[m] * 128 + tid];
                if (tid < 32) sat_out[so + 256 + tid] = sw1t[tid * 4 + m];
            }
        }
#pragma unroll
        for (int k = 0; k < 32; k++) {
            float4 w4 = *(const float4*)&sw1t[k * 4];
            z[0] = fmaf(w4.x, W3c[k], z[0]);
            z[1] = fmaf(w4.y, W3c[k], z[1]);
            z[2] = fmaf(w4.z, W3c[k], z[2]);
            z[3] = fmaf(w4.w, W3c[k], z[3]);
        }
#pragma unroll
        for (int m = 0; m < 4; m++) {
            float inw = z[m] > 0.f ? z[m] : 0.1f * z[m];
            float v = inw * wa;
#pragma unroll
            for (int o = 16; o; o >>= 1) v += __shfl_xor_sync(0xffffffffu, v, o);
            if (lane == 0) red[warp][m] = v;
        }
        __syncthreads();
        if (tid < 4) {
            float att = red[0][tid] + red[1][tid] + red[2][tid] + red[3][tid];
            satt[tid] = att;
            if (tid < nE) g_logits[e0 + tid] = att;
        }
        __syncthreads();
        if (tid < 32) {
#pragma unroll
            for (int m = 0; m < 4; m++)
                if (m < nE)
                    g_w2[(size_t)(e0 + m) * 32 + tid] = satt[m] * sw1t[tid * 4 + m];
        }
        __syncthreads();
    }
}

// ---------------- K5: segment softmax + weighted aggregate (warp/node) -------
// writes directly into Acat[:, 0:160]
__global__ void segment_kernel(const int* __restrict__ src, int Nn) {
    int warp = (blockIdx.x * blockDim.x + threadIdx.x) >> 5;
    int lane = threadIdx.x & 31;
    if (warp >= Nn) return;
    int s0 = g_rowstart[warp], s1 = g_rowstart[warp + 1];
    float acc[5] = {0.f, 0.f, 0.f, 0.f, 0.f};
    if (s1 > s0) {
        float m = -INFINITY;
        for (int e = s0 + lane; e < s1; e += 32) m = fmaxf(m, g_logits[e]);
#pragma unroll
        for (int o = 16; o; o >>= 1) m = fmaxf(m, __shfl_xor_sync(0xffffffffu, m, o));
        float den = 0.f;
        for (int e = s0 + lane; e < s1; e += 32) den += expf(g_logits[e] - m);
#pragma unroll
        for (int o = 16; o; o >>= 1) den += __shfl_xor_sync(0xffffffffu, den, o);
        float inv = 1.0f / den;
        for (int e = s0; e < s1; e++) {
            float alpha = expf(g_logits[e] - m) * inv;
            int sidx = src[e];
#pragma unroll
            for (int i = 0; i < 4; i++)
                acc[i] = fmaf(alpha, g_hn[(size_t)sidx * 128 + lane + 32 * i], acc[i]);
            acc[4] = fmaf(alpha, g_w2[(size_t)e * 32 + lane], acc[4]);
        }
    }
#pragma unroll
    for (int i = 0; i < 4; i++) g_Acat[(size_t)warp * 288 + lane + 32 * i] = acc[i];
    g_Acat[(size_t)warp * 288 + 128 + lane] = acc[4];
}

// ---------------- fill Acat[:, 160:288] = hn ----------------
__global__ void acat_fill(int Nn) {
    int idx = blockIdx.x * blockDim.x + threadIdx.x;
    if (idx >= Nn * 128) return;
    int r = idx >> 7, c = idx & 127;
    g_Acat[(size_t)r * 288 + 160 + c] = g_hn[idx];
}

// ---------------- fixup: hnew = hn where deg == 0 ----------------
__global__ void hnew_fixup(float* __restrict__ hnew, int Nn) {
    int idx = blockIdx.x * blockDim.x + threadIdx.x;
    if (idx >= Nn * 128) return;
    int r = idx >> 7;
    if (g_rowstart[r + 1] == g_rowstart[r]) hnew[idx] = g_hn[idx];
}

// ---------------- fold BN into W_aggre[256:320] ----------------
__global__ void prep_wmod(const float* __restrict__ Wag3,
                          const float* __restrict__ gamma, const float* __restrict__ beta,
                          const float* __restrict__ mean,  const float* __restrict__ var) {
    int c = threadIdx.x;  // 128
    float cv = 0.f;
    for (int k = 0; k < 32; k++) {
        float sc = gamma[k] * rsqrtf(var[k] + 1e-5f);
        float wv = Wag3[k * 128 + c];
        g_Wmod[k * 128 + c] = wv * sc;
        cv = fmaf(beta[k] - mean[k] * sc, wv, cv);
    }
    for (int k = 0; k < 32; k++)
        g_Wmod[(32 + k) * 128 + c] = Wag3[(32 + k) * 128 + c];
    g_cvec[c] = cv;
}

// ---------------- K9: wout = Q1[s]+Q2[d]+cvec + [w2,ow]@Wmod -----------------
__global__ __launch_bounds__(128)
void edge_out_v2(const int* __restrict__ src, const int* __restrict__ dst,
                 float* __restrict__ wout, int E) {
    int tid = threadIdx.x;
    float Wc[64];
#pragma unroll
    for (int k = 0; k < 64; k++) Wc[k] = g_Wmod[k * 128 + tid];
    float cv = g_cvec[tid];
    __shared__ float svt[64 * 4];  // [k][m]
    __shared__ int   sidx[8];

    for (int e0 = blockIdx.x * 4; e0 < E; e0 += gridDim.x * 4) {
        int nE = E - e0; if (nE > 4) nE = 4;
        if (tid < 8) {
            int m = tid >> 1;
            int ee = e0 + (m < nE ? m : nE - 1);
            sidx[tid] = (tid & 1) ? dst[ee] : src[ee];
        }
#pragma unroll
        for (int j = 0; j < 2; j++) {
            int idx = tid + 128 * j;     // 0..255
            int m = idx >> 6, k = idx & 63;
            int mm = m < nE ? m : nE - 1;
            float v = (k < 32) ? g_w2[(size_t)(e0 + mm) * 32 + k]
                               : g_ow[(size_t)(e0 + mm) * 32 + (k - 32)];
            svt[k * 4 + m] = v;
        }
        __syncthreads();
        float acc[4];
#pragma unroll
        for (int m = 0; m < 4; m++)
            acc[m] = g_Q1[(size_t)sidx[m * 2] * 128 + tid]
                   + g_Q2[(size_t)sidx[m * 2 + 1] * 128 + tid] + cv;
#pragma unroll
        for (int k = 0; k < 64; k++) {
            float4 s4 = *(const float4*)&svt[k * 4];
            acc[0] = fmaf(s4.x, Wc[k], acc[0]);
            acc[1] = fmaf(s4.y, Wc[k], acc[1]);
            acc[2] = fmaf(s4.z, Wc[k], acc[2]);
            acc[3] = fmaf(s4.w, Wc[k], acc[3]);
        }
#pragma unroll
        for (int m = 0; m < 4; m++)
            if (m < nE) wout[(size_t)(e0 + m) * 128 + tid] = acc[m];
        __syncthreads();
    }
}

// ---------------- launch ----------------
extern "C" void kernel_launch(void* const* d_in, const int* in_sizes, int n_in,
                              void* d_out, int out_size) {
    const float* h        = (const float*)d_in[0];
    const float* w        = (const float*)d_in[1];
    const int*   src      = (const int*)d_in[2];
    const int*   dst      = (const int*)d_in[3];
    const float* W_en     = (const float*)d_in[4];
    const float* W_attn   = (const float*)d_in[5];
    const float* W_if     = (const float*)d_in[6];
    const float* b_if     = (const float*)d_in[7];
    const float* W_ee     = (const float*)d_in[8];
    const float* W_sf     = (const float*)d_in[9];
    const float* W_conc   = (const float*)d_in[10];
    const float* b_conc   = (const float*)d_in[11];
    const float* bn_gamma = (const float*)d_in[12];
    const float* bn_beta  = (const float*)d_in[13];
    const float* bn_mean  = (const float*)d_in[14];
    const float* bn_var   = (const float*)d_in[15];
    const float* W_ag     = (const float*)d_in[16];

    int Nn = in_sizes[0] / 128;
    int E  = in_sizes[2];

    float* out_hnew = (float*)d_out;
    float* out_wout = out_hnew + (size_t)Nn * 128;
    float* out_sat  = out_wout + (size_t)E * 128;

    float *hn_p, *P1_p, *P2_p, *Q1_p, *Q2_p, *Acat_p;
    cudaGetSymbolAddress((void**)&hn_p,   g_hn);
    cudaGetSymbolAddress((void**)&P1_p,   g_P1);
    cudaGetSymbolAddress((void**)&P2_p,   g_P2);
    cudaGetSymbolAddress((void**)&Q1_p,   g_Q1);
    cudaGetSymbolAddress((void**)&Q2_p,   g_Q2);
    cudaGetSymbolAddress((void**)&Acat_p, g_Acat);

    int gb = (Nn + 127) / 128;

    rowstart_kernel<<<(Nn + 256) / 256, 256>>>(dst, E, Nn);
    gemm_v2<<<gb, 256>>>(h, W_en, nullptr, hn_p, Nn, 128);
    edge_embed_kernel<<<1024, 256>>>(w, W_ee, W_sf, E);
    gemm_v2<<<gb, 256>>>(hn_p, W_if,             nullptr, P1_p, Nn, 128);
    gemm_v2<<<gb, 256>>>(hn_p, W_if + 128 * 128, nullptr, P2_p, Nn, 128);
    edge_fuse_v2<<<4736, 128>>>(src, dst, W_if + 256 * 128, b_if, W_attn, out_sat, E);
    segment_kernel<<<(Nn + 7) / 8, 256>>>(src, Nn);
    acat_fill<<<(Nn * 128 + 255) / 256, 256>>>(Nn);
    gemm_v2<<<gb, 256>>>(Acat_p, W_conc, b_conc, out_hnew, Nn, 288);
    hnew_fixup<<<(Nn * 128 + 255) / 256, 256>>>(out_hnew, Nn);
    gemm_v2<<<gb, 256>>>(out_hnew, W_ag,             nullptr, Q1_p, Nn, 128);
    gemm_v2<<<gb, 256>>>(out_hnew, W_ag + 128 * 128, nullptr, Q2_p, Nn, 128);
    prep_wmod<<<1, 128>>>(W_ag + 256 * 128, bn_gamma, bn_beta, bn_mean, bn_var);
    edge_out_v2<<<4736, 128>>>(src, dst, out_wout, E);
}

// round 3
// speedup vs baseline: 1.4730x; 1.0018x over previous
#include <cuda_runtime.h>
#include <cuda_bf16.h>
#include <math.h>

#define MAXN 50000
#define MAXE 400000

// ---------------- scratch (device globals) ----------------
__device__ float g_hn[MAXN * 128];
__device__ float g_P1[MAXN * 128];
__device__ float g_P2[MAXN * 128];
__device__ float g_Q1[MAXN * 128];
__device__ float g_Q2[MAXN * 128];
__device__ float g_ow[(size_t)MAXE * 32];
__device__ float g_w1[(size_t)MAXE * 32];
__device__ float g_w2[(size_t)MAXE * 32];
__device__ float g_logits[MAXE];
__device__ float g_Acat[(size_t)MAXN * 288];
__device__ int   g_rowstart[MAXN + 1];
__device__ float g_Wmod[64 * 128];
__device__ float g_cvec[128];

// ---------------- K0: segment boundaries (dst sorted) ----------------
__global__ void rowstart_kernel(const int* __restrict__ dst, int E, int Nn) {
    int n = blockIdx.x * blockDim.x + threadIdx.x;
    if (n > Nn) return;
    int lo = 0, hi = E;
    while (lo < hi) {
        int mid = (lo + hi) >> 1;
        if (dst[mid] < n) lo = mid + 1; else hi = mid;
    }
    g_rowstart[n] = lo;
}

// ---------------- gemm_v2: C[M,128] = A[M,K] @ B[K,128] (+bias) --------------
// 256 threads, tile 128x128, 8x8 per thread, As transposed for float4 LDS.
__global__ __launch_bounds__(256, 2)
void gemm_v2(const float* __restrict__ A, const float* __restrict__ B,
             const float* __restrict__ bias, float* __restrict__ C,
             int M, int K) {
    __shared__ float As[32][132];   // [k][r]
    __shared__ float Bs[32][132];   // [k][c]
    int tid = threadIdx.x;
    int tx = tid & 15;          // 16 col groups
    int ty = tid >> 4;          // 16 row groups
    int row0 = blockIdx.x * 128;

    float acc[2][4][2][4];
#pragma unroll
    for (int a = 0; a < 2; a++)
#pragma unroll
        for (int b = 0; b < 4; b++)
#pragma unroll
            for (int c = 0; c < 2; c++)
#pragma unroll
                for (int d = 0; d < 4; d++) acc[a][b][c][d] = 0.f;

    for (int kc = 0; kc < K; kc += 32) {
        // A tile: 128 rows x 32 k, stored transposed
#pragma unroll
        for (int i = 0; i < 4; i++) {
            int e = tid + 256 * i;           // 0..1023
            int r = e >> 3;
            int kg = e & 7;
            float4 v = make_float4(0.f, 0.f, 0.f, 0.f);
            if (row0 + r < M)
                v = *(const float4*)&A[(size_t)(row0 + r) * K + kc + kg * 4];
            As[kg * 4 + 0][r] = v.x;
            As[kg * 4 + 1][r] = v.y;
            As[kg * 4 + 2][r] = v.z;
            As[kg * 4 + 3][r] = v.w;
        }
        // B tile: 32 k x 128 cols
#pragma unroll
        for (int i = 0; i < 4; i++) {
            int e = tid + 256 * i;           // 0..1023
            int k = e >> 5;
            int cg = e & 31;
            *(float4*)&Bs[k][cg * 4] = *(const float4*)&B[(size_t)(kc + k) * 128 + cg * 4];
        }
        __syncthreads();
#pragma unroll
        for (int k = 0; k < 32; k++) {
            float4 a0 = *(const float4*)&As[k][ty * 4];
            float4 a1 = *(const float4*)&As[k][64 + ty * 4];
            float4 b0 = *(const float4*)&Bs[k][tx * 4];
            float4 b1 = *(const float4*)&Bs[k][64 + tx * 4];
            float av[2][4] = {{a0.x, a0.y, a0.z, a0.w}, {a1.x, a1.y, a1.z, a1.w}};
            float bv[2][4] = {{b0.x, b0.y, b0.z, b0.w}, {b1.x, b1.y, b1.z, b1.w}};
#pragma unroll
            for (int mi = 0; mi < 2; mi++)
#pragma unroll
                for (int j = 0; j < 4; j++)
#pragma unroll
                    for (int ni = 0; ni < 2; ni++)
#pragma unroll
                        for (int c = 0; c < 4; c++)
                            acc[mi][j][ni][c] = fmaf(av[mi][j], bv[ni][c], acc[mi][j][ni][c]);
        }
        __syncthreads();
    }
    // epilogue
    float4 bs0 = make_float4(0.f, 0.f, 0.f, 0.f), bs1 = bs0;
    if (bias) {
        bs0 = *(const float4*)&bias[tx * 4];
        bs1 = *(const float4*)&bias[64 + tx * 4];
    }
#pragma unroll
    for (int mi = 0; mi < 2; mi++)
#pragma unroll
        for (int j = 0; j < 4; j++) {
            int row = row0 + mi * 64 + ty * 4 + j;
            if (row < M) {
                float4 o0 = make_float4(acc[mi][j][0][0] + bs0.x, acc[mi][j][0][1] + bs0.y,
                                        acc[mi][j][0][2] + bs0.z, acc[mi][j][0][3] + bs0.w);
                float4 o1 = make_float4(acc[mi][j][1][0] + bs1.x, acc[mi][j][1][1] + bs1.y,
                                        acc[mi][j][1][2] + bs1.z, acc[mi][j][1][3] + bs1.w);
                *(float4*)&C[(size_t)row * 128 + tx * 4] = o0;
                *(float4*)&C[(size_t)row * 128 + 64 + tx * 4] = o1;
            }
        }
}

// ---------------- K2: ow = w@W_ee ; s = lrelu(ow)@W_sf ; w1 = s*ow -----------
__global__ void edge_embed_kernel(const float* __restrict__ w,
                                  const float* __restrict__ Wee,
                                  const float* __restrict__ Wsf, int E) {
    __shared__ float sWee[1024];
    __shared__ float sWsf[32];
    int tid = threadIdx.x;  // 256
    for (int i = tid; i < 1024; i += 256) sWee[i] = Wee[i];
    if (tid < 32) sWsf[tid] = Wsf[tid];
    __syncthreads();
    int lane = tid & 31;
    float Bcol[32];
#pragma unroll
    for (int k = 0; k < 32; k++) Bcol[k] = sWee[k * 32 + lane];
    float sfj = sWsf[lane];
    int warp   = (blockIdx.x * blockDim.x + tid) >> 5;
    int nwarps = (gridDim.x * blockDim.x) >> 5;
    for (int e = warp; e < E; e += nwarps) {
        float wv = w[(size_t)e * 32 + lane];
        float o = 0.f;
#pragma unroll
        for (int k = 0; k < 32; k++)
            o = fmaf(__shfl_sync(0xffffffffu, wv, k), Bcol[k], o);
        float l = o > 0.f ? o : 0.1f * o;
        float sv = l * sfj;
#pragma unroll
        for (int off = 16; off; off >>= 1) sv += __shfl_xor_sync(0xffffffffu, sv, off);
        g_ow[(size_t)e * 32 + lane] = o;
        g_w1[(size_t)e * 32 + lane] = sv * o;
    }
}

// ---------------- K4: per-edge fuse. Thread owns one output column. ----------
// 128 threads, 4 edges per iteration, W3 column in registers.
__global__ __launch_bounds__(128)
void edge_fuse_v2(const int* __restrict__ src, const int* __restrict__ dst,
                  const float* __restrict__ Wif3, const float* __restrict__ bif,
                  const float* __restrict__ Wattn,
                  float* __restrict__ sat_out, int E) {
    int tid = threadIdx.x;
    float W3c[32];
#pragma unroll
    for (int k = 0; k < 32; k++) W3c[k] = Wif3[k * 128 + tid];
    float wa = Wattn[tid];
    float bb = bif[tid];
    __shared__ float sw1t[32 * 4];  // [k][m]
    __shared__ int   sidx[8];       // {src,dst} x 4
    __shared__ float red[4][4];     // [warp][m]
    __shared__ float satt[4];
    int warp = tid >> 5, lane = tid & 31;

    for (int e0 = blockIdx.x * 4; e0 < E; e0 += gridDim.x * 4) {
        int nE = E - e0; if (nE > 4) nE = 4;
        if (tid < 8) {
            int m = tid >> 1;
            int ee = e0 + (m < nE ? m : nE - 1);
            sidx[tid] = (tid & 1) ? dst[ee] : src[ee];
        }
        {
            int m = tid >> 5, k = tid & 31;
            int mm = m < nE ? m : nE - 1;
            sw1t[k * 4 + m] = g_w1[(size_t)(e0 + mm) * 32 + k];
        }
        __syncthreads();

        int s[4], d[4];
        float z[4];
#pragma unroll
        for (int m = 0; m < 4; m++) {
            s[m] = sidx[m * 2];
            d[m] = sidx[m * 2 + 1];
            z[m] = g_P1[(size_t)s[m] * 128 + tid] + g_P2[(size_t)d[m] * 128 + tid] + bb;
        }
        // sat outputs (hs, hd, w1)
#pragma unroll
        for (int m = 0; m < 4; m++) {
            if (m < nE) {
                size_t so = (size_t)(e0 + m) * 288;
                sat_out[so + tid]       = g_hn[(size_t)s[m] * 128 + tid];
                sat_out[so + 128 + tid] = g_hn[(size_t)d[m] * 128 + tid];
                if (tid < 32) sat_out[so + 256 + tid] = sw1t[tid * 4 + m];
            }
        }
#pragma unroll
        for (int k = 0; k < 32; k++) {
            float4 w4 = *(const float4*)&sw1t[k * 4];
            z[0] = fmaf(w4.x, W3c[k], z[0]);
            z[1] = fmaf(w4.y, W3c[k], z[1]);
            z[2] = fmaf(w4.z, W3c[k], z[2]);
            z[3] = fmaf(w4.w, W3c[k], z[3]);
        }
#pragma unroll
        for (int m = 0; m < 4; m++) {
            float inw = z[m] > 0.f ? z[m] : 0.1f * z[m];
            float v = inw * wa;
#pragma unroll
            for (int o = 16; o; o >>= 1) v += __shfl_xor_sync(0xffffffffu, v, o);
            if (lane == 0) red[warp][m] = v;
        }
        __syncthreads();
        if (tid < 4) {
            float att = red[0][tid] + red[1][tid] + red[2][tid] + red[3][tid];
            satt[tid] = att;
            if (tid < nE) g_logits[e0 + tid] = att;
        }
        __syncthreads();
        if (tid < 32) {
#pragma unroll
            for (int m = 0; m < 4; m++)
                if (m < nE)
                    g_w2[(size_t)(e0 + m) * 32 + tid] = satt[m] * sw1t[tid * 4 + m];
        }
        __syncthreads();
    }
}

// ---------------- K5: segment softmax + weighted aggregate (warp/node) -------
// writes directly into Acat[:, 0:160]
__global__ void segment_kernel(const int* __restrict__ src, int Nn) {
    int warp = (blockIdx.x * blockDim.x + threadIdx.x) >> 5;
    int lane = threadIdx.x & 31;
    if (warp >= Nn) return;
    int s0 = g_rowstart[warp], s1 = g_rowstart[warp + 1];
    float acc[5] = {0.f, 0.f, 0.f, 0.f, 0.f};
    if (s1 > s0) {
        float m = -INFINITY;
        for (int e = s0 + lane; e < s1; e += 32) m = fmaxf(m, g_logits[e]);
#pragma unroll
        for (int o = 16; o; o >>= 1) m = fmaxf(m, __shfl_xor_sync(0xffffffffu, m, o));
        float den = 0.f;
        for (int e = s0 + lane; e < s1; e += 32) den += expf(g_logits[e] - m);
#pragma unroll
        for (int o = 16; o; o >>= 1) den += __shfl_xor_sync(0xffffffffu, den, o);
        float inv = 1.0f / den;
        for (int e = s0; e < s1; e++) {
            float alpha = expf(g_logits[e] - m) * inv;
            int sidx = src[e];
#pragma unroll
            for (int i = 0; i < 4; i++)
                acc[i] = fmaf(alpha, g_hn[(size_t)sidx * 128 + lane + 32 * i], acc[i]);
            acc[4] = fmaf(alpha, g_w2[(size_t)e * 32 + lane], acc[4]);
        }
    }
#pragma unroll
    for (int i = 0; i < 4; i++) g_Acat[(size_t)warp * 288 + lane + 32 * i] = acc[i];
    g_Acat[(size_t)warp * 288 + 128 + lane] = acc[4];
}

// ---------------- fill Acat[:, 160:288] = hn ----------------
__global__ void acat_fill(int Nn) {
    int idx = blockIdx.x * blockDim.x + threadIdx.x;
    if (idx >= Nn * 128) return;
    int r = idx >> 7, c = idx & 127;
    g_Acat[(size_t)r * 288 + 160 + c] = g_hn[idx];
}

// ---------------- fixup: hnew = hn where deg == 0 ----------------
__global__ void hnew_fixup(float* __restrict__ hnew, int Nn) {
    int idx = blockIdx.x * blockDim.x + threadIdx.x;
    if (idx >= Nn * 128) return;
    int r = idx >> 7;
    if (g_rowstart[r + 1] == g_rowstart[r]) hnew[idx] = g_hn[idx];
}

// ---------------- fold BN into W_aggre[256:320] ----------------
__global__ void prep_wmod(const float* __restrict__ Wag3,
                          const float* __restrict__ gamma, const float* __restrict__ beta,
                          const float* __restrict__ mean,  const float* __restrict__ var) {
    int c = threadIdx.x;  // 128
    float cv = 0.f;
    for (int k = 0; k < 32; k++) {
        float sc = gamma[k] * rsqrtf(var[k] + 1e-5f);
        float wv = Wag3[k * 128 + c];
        g_Wmod[k * 128 + c] = wv * sc;
        cv = fmaf(beta[k] - mean[k] * sc, wv, cv);
    }
    for (int k = 0; k < 32; k++)
        g_Wmod[(32 + k) * 128 + c] = Wag3[(32 + k) * 128 + c];
    g_cvec[c] = cv;
}

// ---------------- K9: wout = Q1[s]+Q2[d]+cvec + [w2,ow]@Wmod -----------------
__global__ __launch_bounds__(128)
void edge_out_v2(const int* __restrict__ src, const int* __restrict__ dst,
                 float* __restrict__ wout, int E) {
    int tid = threadIdx.x;
    float Wc[64];
#pragma unroll
    for (int k = 0; k < 64; k++) Wc[k] = g_Wmod[k * 128 + tid];
    float cv = g_cvec[tid];
    __shared__ float svt[64 * 4];  // [k][m]
    __shared__ int   sidx[8];

    for (int e0 = blockIdx.x * 4; e0 < E; e0 += gridDim.x * 4) {
        int nE = E - e0; if (nE > 4) nE = 4;
        if (tid < 8) {
            int m = tid >> 1;
            int ee = e0 + (m < nE ? m : nE - 1);
            sidx[tid] = (tid & 1) ? dst[ee] : src[ee];
        }
#pragma unroll
        for (int j = 0; j < 2; j++) {
            int idx = tid + 128 * j;     // 0..255
            int m = idx >> 6, k = idx & 63;
            int mm = m < nE ? m : nE - 1;
            float v = (k < 32) ? g_w2[(size_t)(e0 + mm) * 32 + k]
                               : g_ow[(size_t)(e0 + mm) * 32 + (k - 32)];
            svt[k * 4 + m] = v;
        }
        __syncthreads();
        float acc[4];
#pragma unroll
        for (int m = 0; m < 4; m++)
            acc[m] = g_Q1[(size_t)sidx[m * 2] * 128 + tid]
                   + g_Q2[(size_t)sidx[m * 2 + 1] * 128 + tid] + cv;
#pragma unroll
        for (int k = 0; k < 64; k++) {
            float4 s4 = *(const float4*)&svt[k * 4];
            acc[0] = fmaf(s4.x, Wc[k], acc[0]);
            acc[1] = fmaf(s4.y, Wc[k], acc[1]);
            acc[2] = fmaf(s4.z, Wc[k], acc[2]);
            acc[3] = fmaf(s4.w, Wc[k], acc[3]);
        }
#pragma unroll
        for (int m = 0; m < 4; m++)
            if (m < nE) wout[(size_t)(e0 + m) * 128 + tid] = acc[m];
        __syncthreads();
    }
}

// ---------------- launch ----------------
extern "C" void kernel_launch(void* const* d_in, const int* in_sizes, int n_in,
                              void* d_out, int out_size) {
    const float* h        = (const float*)d_in[0];
    const float* w        = (const float*)d_in[1];
    const int*   src      = (const int*)d_in[2];
    const int*   dst      = (const int*)d_in[3];
    const float* W_en     = (const float*)d_in[4];
    const float* W_attn   = (const float*)d_in[5];
    const float* W_if     = (const float*)d_in[6];
    const float* b_if     = (const float*)d_in[7];
    const float* W_ee     = (const float*)d_in[8];
    const float* W_sf     = (const float*)d_in[9];
    const float* W_conc   = (const float*)d_in[10];
    const float* b_conc   = (const float*)d_in[11];
    const float* bn_gamma = (const float*)d_in[12];
    const float* bn_beta  = (const float*)d_in[13];
    const float* bn_mean  = (const float*)d_in[14];
    const float* bn_var   = (const float*)d_in[15];
    const float* W_ag     = (const float*)d_in[16];

    int Nn = in_sizes[0] / 128;
    int E  = in_sizes[2];

    float* out_hnew = (float*)d_out;
    float* out_wout = out_hnew + (size_t)Nn * 128;
    float* out_sat  = out_wout + (size_t)E * 128;

    float *hn_p, *P1_p, *P2_p, *Q1_p, *Q2_p, *Acat_p;
    cudaGetSymbolAddress((void**)&hn_p,   g_hn);
    cudaGetSymbolAddress((void**)&P1_p,   g_P1);
    cudaGetSymbolAddress((void**)&P2_p,   g_P2);
    cudaGetSymbolAddress((void**)&Q1_p,   g_Q1);
    cudaGetSymbolAddress((void**)&Q2_p,   g_Q2);
    cudaGetSymbolAddress((void**)&Acat_p, g_Acat);

    int gb = (Nn + 127) / 128;

    rowstart_kernel<<<(Nn + 256) / 256, 256>>>(dst, E, Nn);
    gemm_v2<<<gb, 256>>>(h, W_en, nullptr, hn_p, Nn, 128);
    edge_embed_kernel<<<1024, 256>>>(w, W_ee, W_sf, E);
    gemm_v2<<<gb, 256>>>(hn_p, W_if,             nullptr, P1_p, Nn, 128);
    gemm_v2<<<gb, 256>>>(hn_p, W_if + 128 * 128, nullptr, P2_p, Nn, 128);
    edge_fuse_v2<<<4736, 128>>>(src, dst, W_if + 256 * 128, b_if, W_attn, out_sat, E);
    segment_kernel<<<(Nn + 7) / 8, 256>>>(src, Nn);
    acat_fill<<<(Nn * 128 + 255) / 256, 256>>>(Nn);
    gemm_v2<<<gb, 256>>>(Acat_p, W_conc, b_conc, out_hnew, Nn, 288);
    hnew_fixup<<<(Nn * 128 + 255) / 256, 256>>>(out_hnew, Nn);
    gemm_v2<<<gb, 256>>>(out_hnew, W_ag,             nullptr, Q1_p, Nn, 128);
    gemm_v2<<<gb, 256>>>(out_hnew, W_ag + 128 * 128, nullptr, Q2_p, Nn, 128);
    prep_wmod<<<1, 128>>>(W_ag + 256 * 128, bn_gamma, bn_beta, bn_mean, bn_var);
    edge_out_v2<<<4736, 128>>>(src, dst, out_wout, E);
}

// round 4
// speedup vs baseline: 1.8511x; 1.2567x over previous
#include <cuda_runtime.h>
#include <cuda_bf16.h>
#include <math.h>

#define MAXN 50000
#define MAXE 400000

// ---------------- scratch (device globals) ----------------
__device__ float g_hn[MAXN * 128];
__device__ float g_P1[MAXN * 128];
__device__ float g_P2[MAXN * 128];
__device__ float g_Q1[MAXN * 128];
__device__ float g_Q2[MAXN * 128];
__device__ float g_ow[(size_t)MAXE * 32];
__device__ float g_s[MAXE];
__device__ float g_aw[MAXE];
__device__ float g_logits[MAXE];
__device__ float g_G1[(size_t)MAXE * 128];
__device__ float g_G2[(size_t)MAXE * 128];
__device__ float g_G3[(size_t)MAXE * 128];
__device__ float g_Acat[(size_t)MAXN * 288];
__device__ int   g_rowstart[MAXN + 1];
__device__ float g_C1[32 * 128];
__device__ float g_C2[32 * 128];
__device__ float g_C3[32 * 128];
__device__ float g_cvec[128];

// ---------------- f32x2 packed helpers ----------------
__device__ __forceinline__ unsigned long long pk2(float x, float y) {
    unsigned long long r;
    asm("mov.b64 %0, {%1, %2};" : "=l"(r) : "f"(x), "f"(y));
    return r;
}
__device__ __forceinline__ unsigned long long ffma2(unsigned long long a,
                                                    unsigned long long b,
                                                    unsigned long long c) {
    unsigned long long d;
    asm("fma.rn.f32x2 %0, %1, %2, %3;" : "=l"(d) : "l"(a), "l"(b), "l"(c));
    return d;
}
__device__ __forceinline__ unsigned long long fadd2(unsigned long long a,
                                                    unsigned long long b) {
    unsigned long long d;
    asm("add.rn.f32x2 %0, %1, %2;" : "=l"(d) : "l"(a), "l"(b));
    return d;
}

// ---------------- K0: segment boundaries (dst sorted) ----------------
__global__ void rowstart_kernel(const int* __restrict__ dst, int E, int Nn) {
    int n = blockIdx.x * blockDim.x + threadIdx.x;
    if (n > Nn) return;
    int lo = 0, hi = E;
    while (lo < hi) {
        int mid = (lo + hi) >> 1;
        if (dst[mid] < n) lo = mid + 1; else hi = mid;
    }
    g_rowstart[n] = lo;
}

// ---------------- prep: combined 32x128 matrices + BN fold ----------------
__global__ void prep_cmat(const float* __restrict__ W3,    // W_if rows 256..287
                          const float* __restrict__ Wag3,  // W_ag rows 256..319
                          const float* __restrict__ Wee,   // 32x32
                          const float* __restrict__ gamma, const float* __restrict__ beta,
                          const float* __restrict__ mean,  const float* __restrict__ var) {
    int c = threadIdx.x;  // 128
    __shared__ float sWee[1024];
    __shared__ float ssc[32];
    for (int i = c; i < 1024; i += 128) sWee[i] = Wee[i];
    if (c < 32) ssc[c] = gamma[c] * rsqrtf(var[c] + 1e-5f);
    __syncthreads();
    for (int k = 0; k < 32; k++) {
        float a3 = 0.f, a1 = 0.f, a2 = 0.f;
        for (int j = 0; j < 32; j++) {
            float wk = sWee[k * 32 + j];
            a3 = fmaf(wk, W3[j * 128 + c], a3);
            a1 = fmaf(wk, Wag3[j * 128 + c] * ssc[j], a1);
            a2 = fmaf(wk, Wag3[(32 + j) * 128 + c], a2);
        }
        g_C3[k * 128 + c] = a3;
        g_C1[k * 128 + c] = a1;
        g_C2[k * 128 + c] = a2;
    }
    float cv = 0.f;
    for (int j = 0; j < 32; j++)
        cv = fmaf(beta[j] - mean[j] * ssc[j], Wag3[j * 128 + c], cv);
    g_cvec[c] = cv;
}

// ---------------- gemm_v3: C[M,128] = A[M,K] @ B[K,128] (+bias), f32x2 ------
// 256 threads, tile 128x128, 8 rows x 8 cols (4 col-pairs) per thread.
__global__ __launch_bounds__(256, 2)
void gemm_v3(const float* __restrict__ A, const float* __restrict__ B,
             const float* __restrict__ bias, float* __restrict__ C,
             int M, int K) {
    __shared__ float As[32][132];   // [k][r] transposed
    __shared__ float Bs[32][132];   // [k][c]
    int tid = threadIdx.x;
    int tx = tid & 15;
    int ty = tid >> 4;
    int row0 = blockIdx.x * 128;

    unsigned long long acc[2][4][2][2];  // [mhalf][rowj][nhalf][colpair]
#pragma unroll
    for (int a = 0; a < 2; a++)
#pragma unroll
        for (int b = 0; b < 4; b++)
#pragma unroll
            for (int c = 0; c < 2; c++)
#pragma unroll
                for (int d = 0; d < 2; d++) acc[a][b][c][d] = 0ull;

    for (int kc = 0; kc < K; kc += 32) {
#pragma unroll
        for (int i = 0; i < 4; i++) {
            int e = tid + 256 * i;
            int r = e >> 3;
            int kg = e & 7;
            float4 v = make_float4(0.f, 0.f, 0.f, 0.f);
            if (row0 + r < M)
                v = *(const float4*)&A[(size_t)(row0 + r) * K + kc + kg * 4];
            As[kg * 4 + 0][r] = v.x;
            As[kg * 4 + 1][r] = v.y;
            As[kg * 4 + 2][r] = v.z;
            As[kg * 4 + 3][r] = v.w;
        }
#pragma unroll
        for (int i = 0; i < 4; i++) {
            int e = tid + 256 * i;
            int k = e >> 5;
            int cg = e & 31;
            *(float4*)&Bs[k][cg * 4] = *(const float4*)&B[(size_t)(kc + k) * 128 + cg * 4];
        }
        __syncthreads();
#pragma unroll
        for (int k = 0; k < 32; k++) {
            float4 af0 = *(const float4*)&As[k][ty * 4];
            float4 af1 = *(const float4*)&As[k][64 + ty * 4];
            ulonglong2 b0 = *(const ulonglong2*)&Bs[k][tx * 4];
            ulonglong2 b1 = *(const ulonglong2*)&Bs[k][64 + tx * 4];
            float av[2][4] = {{af0.x, af0.y, af0.z, af0.w}, {af1.x, af1.y, af1.z, af1.w}};
#pragma unroll
            for (int mi = 0; mi < 2; mi++)
#pragma unroll
                for (int j = 0; j < 4; j++) {
                    unsigned long long ap = pk2(av[mi][j], av[mi][j]);
                    acc[mi][j][0][0] = ffma2(ap, b0.x, acc[mi][j][0][0]);
                    acc[mi][j][0][1] = ffma2(ap, b0.y, acc[mi][j][0][1]);
                    acc[mi][j][1][0] = ffma2(ap, b1.x, acc[mi][j][1][0]);
                    acc[mi][j][1][1] = ffma2(ap, b1.y, acc[mi][j][1][1]);
                }
        }
        __syncthreads();
    }
    // epilogue
    ulonglong2 bp0 = {0ull, 0ull}, bp1 = {0ull, 0ull};
    if (bias) {
        bp0 = *(const ulonglong2*)&bias[tx * 4];
        bp1 = *(const ulonglong2*)&bias[64 + tx * 4];
    }
#pragma unroll
    for (int mi = 0; mi < 2; mi++)
#pragma unroll
        for (int j = 0; j < 4; j++) {
            int row = row0 + mi * 64 + ty * 4 + j;
            if (row < M) {
                ulonglong2 o0, o1;
                o0.x = fadd2(acc[mi][j][0][0], bp0.x);
                o0.y = fadd2(acc[mi][j][0][1], bp0.y);
                o1.x = fadd2(acc[mi][j][1][0], bp1.x);
                o1.y = fadd2(acc[mi][j][1][1], bp1.y);
                *(ulonglong2*)&C[(size_t)row * 128 + tx * 4] = o0;
                *(ulonglong2*)&C[(size_t)row * 128 + 64 + tx * 4] = o1;
            }
        }
}

// ---------------- K2: ow = w@W_ee ; s = lrelu(ow)@W_sf (scalar) -------------
__global__ void edge_embed_kernel(const float* __restrict__ w,
                                  const float* __restrict__ Wee,
                                  const float* __restrict__ Wsf, int E) {
    __shared__ float sWee[1024];
    __shared__ float sWsf[32];
    int tid = threadIdx.x;  // 256
    for (int i = tid; i < 1024; i += 256) sWee[i] = Wee[i];
    if (tid < 32) sWsf[tid] = Wsf[tid];
    __syncthreads();
    int lane = tid & 31;
    float Bcol[32];
#pragma unroll
    for (int k = 0; k < 32; k++) Bcol[k] = sWee[k * 32 + lane];
    float sfj = sWsf[lane];
    int warp   = (blockIdx.x * blockDim.x + tid) >> 5;
    int nwarps = (gridDim.x * blockDim.x) >> 5;
    for (int e = warp; e < E; e += nwarps) {
        float wv = w[(size_t)e * 32 + lane];
        float o = 0.f;
#pragma unroll
        for (int k = 0; k < 32; k++)
            o = fmaf(__shfl_sync(0xffffffffu, wv, k), Bcol[k], o);
        float l = o > 0.f ? o : 0.1f * o;
        float sv = l * sfj;
#pragma unroll
        for (int off = 16; off; off >>= 1) sv += __shfl_xor_sync(0xffffffffu, sv, off);
        g_ow[(size_t)e * 32 + lane] = o;
        if (lane == 0) g_s[e] = sv;
    }
}

// ---------------- K4: edge fuse — warp per edge, no block syncs -------------
// z = P1[s]+P2[d]+b+s_e*G1[e]; att = lrelu(z)@W_attn; sat; aw = att*s
__global__ __launch_bounds__(256)
void edge_fuse_v3(const int* __restrict__ src, const int* __restrict__ dst,
                  const float* __restrict__ bif, const float* __restrict__ Wattn,
                  float* __restrict__ sat_out, int E) {
    int lane = threadIdx.x & 31;
    int warp   = (blockIdx.x * blockDim.x + threadIdx.x) >> 5;
    int nwarps = (gridDim.x * blockDim.x) >> 5;
    float4 b4  = *(const float4*)&bif[lane * 4];
    float4 wa4 = *(const float4*)&Wattn[lane * 4];
    for (int e = warp; e < E; e += nwarps) {
        int s = src[e], d = dst[e];
        float se = g_s[e];
        float4 p1 = *(const float4*)&g_P1[(size_t)s * 128 + lane * 4];
        float4 p2 = *(const float4*)&g_P2[(size_t)d * 128 + lane * 4];
        float4 g1 = *(const float4*)&g_G1[(size_t)e * 128 + lane * 4];
        float4 hs = *(const float4*)&g_hn[(size_t)s * 128 + lane * 4];
        float4 hd = *(const float4*)&g_hn[(size_t)d * 128 + lane * 4];
        float zx = p1.x + p2.x + b4.x + se * g1.x;
        float zy = p1.y + p2.y + b4.y + se * g1.y;
        float zz = p1.z + p2.z + b4.z + se * g1.z;
        float zw = p1.w + p2.w + b4.w + se * g1.w;
        float ix = zx > 0.f ? zx : 0.1f * zx;
        float iy = zy > 0.f ? zy : 0.1f * zy;
        float iz = zz > 0.f ? zz : 0.1f * zz;
        float iw = zw > 0.f ? zw : 0.1f * zw;
        float v = ix * wa4.x + iy * wa4.y + iz * wa4.z + iw * wa4.w;
#pragma unroll
        for (int o = 16; o; o >>= 1) v += __shfl_xor_sync(0xffffffffu, v, o);
        size_t so = (size_t)e * 288;
        *(float4*)&sat_out[so + lane * 4]       = hs;
        *(float4*)&sat_out[so + 128 + lane * 4] = hd;
        if (lane < 8) {
            float4 ow4 = *(const float4*)&g_ow[(size_t)e * 32 + lane * 4];
            float4 w14 = make_float4(se * ow4.x, se * ow4.y, se * ow4.z, se * ow4.w);
            *(float4*)&sat_out[so + 256 + lane * 4] = w14;
        }
        if (lane == 0) {
            g_logits[e] = v;
            g_aw[e] = v * se;
        }
    }
}

// ---------------- K5: segment softmax + aggregate (warp per node) -----------
__global__ void segment_kernel(const int* __restrict__ src, int Nn) {
    int warp = (blockIdx.x * blockDim.x + threadIdx.x) >> 5;
    int lane = threadIdx.x & 31;
    if (warp >= Nn) return;
    int s0 = g_rowstart[warp], s1 = g_rowstart[warp + 1];
    float acc[5] = {0.f, 0.f, 0.f, 0.f, 0.f};
    if (s1 > s0) {
        float m = -INFINITY;
        for (int e = s0 + lane; e < s1; e += 32) m = fmaxf(m, g_logits[e]);
#pragma unroll
        for (int o = 16; o; o >>= 1) m = fmaxf(m, __shfl_xor_sync(0xffffffffu, m, o));
        float den = 0.f;
        for (int e = s0 + lane; e < s1; e += 32) den += expf(g_logits[e] - m);
#pragma unroll
        for (int o = 16; o; o >>= 1) den += __shfl_xor_sync(0xffffffffu, den, o);
        float inv = 1.0f / den;
        for (int e = s0; e < s1; e++) {
            float alpha = expf(g_logits[e] - m) * inv;
            int sidx = src[e];
#pragma unroll
            for (int i = 0; i < 4; i++)
                acc[i] = fmaf(alpha, g_hn[(size_t)sidx * 128 + lane + 32 * i], acc[i]);
            acc[4] = fmaf(alpha * g_aw[e], g_ow[(size_t)e * 32 + lane], acc[4]);
        }
    }
#pragma unroll
    for (int i = 0; i < 4; i++) g_Acat[(size_t)warp * 288 + lane + 32 * i] = acc[i];
    g_Acat[(size_t)warp * 288 + 128 + lane] = acc[4];
}

// ---------------- fill Acat[:, 160:288] = hn ----------------
__global__ void acat_fill(int Nn) {
    int idx = blockIdx.x * blockDim.x + threadIdx.x;
    if (idx >= Nn * 128) return;
    int r = idx >> 7, c = idx & 127;
    g_Acat[(size_t)r * 288 + 160 + c] = g_hn[idx];
}

// ---------------- fixup: hnew = hn where deg == 0 ----------------
__global__ void hnew_fixup(float* __restrict__ hnew, int Nn) {
    int idx = blockIdx.x * blockDim.x + threadIdx.x;
    if (idx >= Nn * 128) return;
    int r = idx >> 7;
    if (g_rowstart[r + 1] == g_rowstart[r]) hnew[idx] = g_hn[idx];
}

// ---------------- K9: edge out — warp per edge, pure gather+axpy ------------
// wout = Q1[s]+Q2[d]+cvec + aw_e*G2[e] + G3[e]
__global__ __launch_bounds__(256)
void edge_out_v3(const int* __restrict__ src, const int* __restrict__ dst,
                 float* __restrict__ wout, int E) {
    int lane = threadIdx.x & 31;
    int warp   = (blockIdx.x * blockDim.x + threadIdx.x) >> 5;
    int nwarps = (gridDim.x * blockDim.x) >> 5;
    float4 cv4 = *(const float4*)&g_cvec[lane * 4];
    for (int e = warp; e < E; e += nwarps) {
        int s = src[e], d = dst[e];
        float aw = g_aw[e];
        float4 q1 = *(const float4*)&g_Q1[(size_t)s * 128 + lane * 4];
        float4 q2 = *(const float4*)&g_Q2[(size_t)d * 128 + lane * 4];
        float4 g2 = *(const float4*)&g_G2[(size_t)e * 128 + lane * 4];
        float4 g3 = *(const float4*)&g_G3[(size_t)e * 128 + lane * 4];
        float4 o;
        o.x = q1.x + q2.x + cv4.x + aw * g2.x + g3.x;
        o.y = q1.y + q2.y + cv4.y + aw * g2.y + g3.y;
        o.z = q1.z + q2.z + cv4.z + aw * g2.z + g3.z;
        o.w = q1.w + q2.w + cv4.w + aw * g2.w + g3.w;
        *(float4*)&wout[(size_t)e * 128 + lane * 4] = o;
    }
}

// ---------------- launch ----------------
extern "C" void kernel_launch(void* const* d_in, const int* in_sizes, int n_in,
                              void* d_out, int out_size) {
    const float* h        = (const float*)d_in[0];
    const float* w        = (const float*)d_in[1];
    const int*   src      = (const int*)d_in[2];
    const int*   dst      = (const int*)d_in[3];
    const float* W_en     = (const float*)d_in[4];
    const float* W_attn   = (const float*)d_in[5];
    const float* W_if     = (const float*)d_in[6];
    const float* b_if     = (const float*)d_in[7];
    const float* W_ee     = (const float*)d_in[8];
    const float* W_sf     = (const float*)d_in[9];
    const float* W_conc   = (const float*)d_in[10];
    const float* b_conc   = (const float*)d_in[11];
    const float* bn_gamma = (const float*)d_in[12];
    const float* bn_beta  = (const float*)d_in[13];
    const float* bn_mean  = (const float*)d_in[14];
    const float* bn_var   = (const float*)d_in[15];
    const float* W_ag     = (const float*)d_in[16];

    int Nn = in_sizes[0] / 128;
    int E  = in_sizes[2];

    float* out_hnew = (float*)d_out;
    float* out_wout = out_hnew + (size_t)Nn * 128;
    float* out_sat  = out_wout + (size_t)E * 128;

    float *hn_p, *P1_p, *P2_p, *Q1_p, *Q2_p, *Acat_p, *G1_p, *G2_p, *G3_p;
    float *C1_p, *C2_p, *C3_p;
    cudaGetSymbolAddress((void**)&hn_p,   g_hn);
    cudaGetSymbolAddress((void**)&P1_p,   g_P1);
    cudaGetSymbolAddress((void**)&P2_p,   g_P2);
    cudaGetSymbolAddress((void**)&Q1_p,   g_Q1);
    cudaGetSymbolAddress((void**)&Q2_p,   g_Q2);
    cudaGetSymbolAddress((void**)&Acat_p, g_Acat);
    cudaGetSymbolAddress((void**)&G1_p,   g_G1);
    cudaGetSymbolAddress((void**)&G2_p,   g_G2);
    cudaGetSymbolAddress((void**)&G3_p,   g_G3);
    cudaGetSymbolAddress((void**)&C1_p,   g_C1);
    cudaGetSymbolAddress((void**)&C2_p,   g_C2);
    cudaGetSymbolAddress((void**)&C3_p,   g_C3);

    int gbN = (Nn + 127) / 128;
    int gbE = (E + 127) / 128;

    rowstart_kernel<<<(Nn + 256) / 256, 256>>>(dst, E, Nn);
    prep_cmat<<<1, 128>>>(W_if + 256 * 128, W_ag + 256 * 128, W_ee,
                          bn_gamma, bn_beta, bn_mean, bn_var);
    gemm_v3<<<gbN, 256>>>(h, W_en, nullptr, hn_p, Nn, 128);
    edge_embed_kernel<<<1024, 256>>>(w, W_ee, W_sf, E);
    gemm_v3<<<gbE, 256>>>(w, C3_p, nullptr, G1_p, E, 32);
    gemm_v3<<<gbE, 256>>>(w, C1_p, nullptr, G2_p, E, 32);
    gemm_v3<<<gbE, 256>>>(w, C2_p, nullptr, G3_p, E, 32);
    gemm_v3<<<gbN, 256>>>(hn_p, W_if,             nullptr, P1_p, Nn, 128);
    gemm_v3<<<gbN, 256>>>(hn_p, W_if + 128 * 128, nullptr, P2_p, Nn, 128);
    edge_fuse_v3<<<2048, 256>>>(src, dst, b_if, W_attn, out_sat, E);
    segment_kernel<<<(Nn + 7) / 8, 256>>>(src, Nn);
    acat_fill<<<(Nn * 128 + 255) / 256, 256>>>(Nn);
    gemm_v3<<<gbN, 256>>>(Acat_p, W_conc, b_conc, out_hnew, Nn, 288);
    hnew_fixup<<<(Nn * 128 + 255) / 256, 256>>>(out_hnew, Nn);
    gemm_v3<<<gbN, 256>>>(out_hnew, W_ag,             nullptr, Q1_p, Nn, 128);
    gemm_v3<<<gbN, 256>>>(out_hnew, W_ag + 128 * 128, nullptr, Q2_p, Nn, 128);
    edge_out_v3<<<2048, 256>>>(src, dst, out_wout, E);
}

// round 5
// speedup vs baseline: 2.1397x; 1.1559x over previous
#include <cuda_runtime.h>
#include <cuda_bf16.h>
#include <math.h>

#define MAXN 50000
#define MAXE 400000

// ---------------- scratch (device globals) ----------------
__device__ float g_hn[MAXN * 128];
__device__ float g_P1[MAXN * 128];
__device__ float g_P2[MAXN * 128];
__device__ float g_Q1[MAXN * 128];
__device__ float g_Q2[MAXN * 128];
__device__ float g_ow[(size_t)MAXE * 32];
__device__ float g_A1[(size_t)MAXE * 32];
__device__ float g_s[MAXE];
__device__ float g_aw[MAXE];
__device__ float g_logits[MAXE];
__device__ float g_Acat[(size_t)MAXN * 288];
__device__ int   g_rowstart[MAXN + 1];
__device__ float g_C1[32 * 128];
__device__ float g_C2[32 * 128];
__device__ float g_C3[32 * 128];
__device__ float g_cvec[128];

// ---------------- f32x2 packed helpers ----------------
__device__ __forceinline__ unsigned long long pk2(float x, float y) {
    unsigned long long r;
    asm("mov.b64 %0, {%1, %2};" : "=l"(r) : "f"(x), "f"(y));
    return r;
}
__device__ __forceinline__ unsigned long long ffma2(unsigned long long a,
                                                    unsigned long long b,
                                                    unsigned long long c) {
    unsigned long long d;
    asm("fma.rn.f32x2 %0, %1, %2, %3;" : "=l"(d) : "l"(a), "l"(b), "l"(c));
    return d;
}
__device__ __forceinline__ unsigned long long fadd2(unsigned long long a,
                                                    unsigned long long b) {
    unsigned long long d;
    asm("add.rn.f32x2 %0, %1, %2;" : "=l"(d) : "l"(a), "l"(b));
    return d;
}
__device__ __forceinline__ void upk2(float& lo, float& hi, unsigned long long v) {
    asm("mov.b64 {%0, %1}, %2;" : "=f"(lo), "=f"(hi) : "l"(v));
}

// ---------------- K0: segment boundaries (dst sorted) ----------------
__global__ void rowstart_kernel(const int* __restrict__ dst, int E, int Nn) {
    int n = blockIdx.x * blockDim.x + threadIdx.x;
    if (n > Nn) return;
    int lo = 0, hi = E;
    while (lo < hi) {
        int mid = (lo + hi) >> 1;
        if (dst[mid] < n) lo = mid + 1; else hi = mid;
    }
    g_rowstart[n] = lo;
}

// ---------------- prep: combined 32x128 matrices + BN fold ----------------
__global__ void prep_cmat(const float* __restrict__ W3,    // W_if rows 256..287
                          const float* __restrict__ Wag3,  // W_ag rows 256..319
                          const float* __restrict__ Wee,   // 32x32
                          const float* __restrict__ gamma, const float* __restrict__ beta,
                          const float* __restrict__ mean,  const float* __restrict__ var) {
    int c = threadIdx.x;  // 128
    __shared__ float sWee[1024];
    __shared__ float ssc[32];
    for (int i = c; i < 1024; i += 128) sWee[i] = Wee[i];
    if (c < 32) ssc[c] = gamma[c] * rsqrtf(var[c] + 1e-5f);
    __syncthreads();
    for (int k = 0; k < 32; k++) {
        float a3 = 0.f, a1 = 0.f, a2 = 0.f;
        for (int j = 0; j < 32; j++) {
            float wk = sWee[k * 32 + j];
            a3 = fmaf(wk, W3[j * 128 + c], a3);
            a1 = fmaf(wk, Wag3[j * 128 + c] * ssc[j], a1);
            a2 = fmaf(wk, Wag3[(32 + j) * 128 + c], a2);
        }
        g_C3[k * 128 + c] = a3;
        g_C1[k * 128 + c] = a1;
        g_C2[k * 128 + c] = a2;
    }
    float cv = 0.f;
    for (int j = 0; j < 32; j++)
        cv = fmaf(beta[j] - mean[j] * ssc[j], Wag3[j * 128 + c], cv);
    g_cvec[c] = cv;
}

// ---------------- gemm_v3: C[M,128] = A[M,K] @ B[K,128] (+bias), f32x2 ------
__global__ __launch_bounds__(256, 2)
void gemm_v3(const float* __restrict__ A, const float* __restrict__ B,
             const float* __restrict__ bias, float* __restrict__ C,
             int M, int K) {
    __shared__ float As[32][132];
    __shared__ float Bs[32][132];
    int tid = threadIdx.x;
    int tx = tid & 15;
    int ty = tid >> 4;
    int row0 = blockIdx.x * 128;

    unsigned long long acc[2][4][2][2];
#pragma unroll
    for (int a = 0; a < 2; a++)
#pragma unroll
        for (int b = 0; b < 4; b++)
#pragma unroll
            for (int c = 0; c < 2; c++)
#pragma unroll
                for (int d = 0; d < 2; d++) acc[a][b][c][d] = 0ull;

    for (int kc = 0; kc < K; kc += 32) {
#pragma unroll
        for (int i = 0; i < 4; i++) {
            int e = tid + 256 * i;
            int r = e >> 3;
            int kg = e & 7;
            float4 v = make_float4(0.f, 0.f, 0.f, 0.f);
            if (row0 + r < M)
                v = *(const float4*)&A[(size_t)(row0 + r) * K + kc + kg * 4];
            As[kg * 4 + 0][r] = v.x;
            As[kg * 4 + 1][r] = v.y;
            As[kg * 4 + 2][r] = v.z;
            As[kg * 4 + 3][r] = v.w;
        }
#pragma unroll
        for (int i = 0; i < 4; i++) {
            int e = tid + 256 * i;
            int k = e >> 5;
            int cg = e & 31;
            *(float4*)&Bs[k][cg * 4] = *(const float4*)&B[(size_t)(kc + k) * 128 + cg * 4];
        }
        __syncthreads();
#pragma unroll
        for (int k = 0; k < 32; k++) {
            float4 af0 = *(const float4*)&As[k][ty * 4];
            float4 af1 = *(const float4*)&As[k][64 + ty * 4];
            ulonglong2 b0 = *(const ulonglong2*)&Bs[k][tx * 4];
            ulonglong2 b1 = *(const ulonglong2*)&Bs[k][64 + tx * 4];
            float av[2][4] = {{af0.x, af0.y, af0.z, af0.w}, {af1.x, af1.y, af1.z, af1.w}};
#pragma unroll
            for (int mi = 0; mi < 2; mi++)
#pragma unroll
                for (int j = 0; j < 4; j++) {
                    unsigned long long ap = pk2(av[mi][j], av[mi][j]);
                    acc[mi][j][0][0] = ffma2(ap, b0.x, acc[mi][j][0][0]);
                    acc[mi][j][0][1] = ffma2(ap, b0.y, acc[mi][j][0][1]);
                    acc[mi][j][1][0] = ffma2(ap, b1.x, acc[mi][j][1][0]);
                    acc[mi][j][1][1] = ffma2(ap, b1.y, acc[mi][j][1][1]);
                }
        }
        __syncthreads();
    }
    ulonglong2 bp0 = {0ull, 0ull}, bp1 = {0ull, 0ull};
    if (bias) {
        bp0 = *(const ulonglong2*)&bias[tx * 4];
        bp1 = *(const ulonglong2*)&bias[64 + tx * 4];
    }
#pragma unroll
    for (int mi = 0; mi < 2; mi++)
#pragma unroll
        for (int j = 0; j < 4; j++) {
            int row = row0 + mi * 64 + ty * 4 + j;
            if (row < M) {
                ulonglong2 o0, o1;
                o0.x = fadd2(acc[mi][j][0][0], bp0.x);
                o0.y = fadd2(acc[mi][j][0][1], bp0.y);
                o1.x = fadd2(acc[mi][j][1][0], bp1.x);
                o1.y = fadd2(acc[mi][j][1][1], bp1.y);
                *(ulonglong2*)&C[(size_t)row * 128 + tx * 4] = o0;
                *(ulonglong2*)&C[(size_t)row * 128 + 64 + tx * 4] = o1;
            }
        }
}

// ---------------- k_embed: ow, s, A1=s*w, sat[:,256:288]=s*ow ---------------
// 256 threads, 128 edges per block. Thread owns one column, warp owns 16 edges.
__global__ __launch_bounds__(256)
void k_embed(const float* __restrict__ w, const float* __restrict__ Wee,
             const float* __restrict__ Wsf, float* __restrict__ sat_out, int E) {
    __shared__ float ws[128][33];
    __shared__ float sB[1024];
    __shared__ float sSf[32];
    int tid = threadIdx.x;
    for (int i = tid; i < 1024; i += 256) sB[i] = Wee[i];
    if (tid < 32) sSf[tid] = Wsf[tid];
    int e0 = blockIdx.x * 128;
#pragma unroll
    for (int i = 0; i < 4; i++) {
        int idx = tid + 256 * i;          // 0..1023 float4 units
        int e = idx >> 3, k4 = idx & 7;
        float4 v = make_float4(0.f, 0.f, 0.f, 0.f);
        if (e0 + e < E) v = *(const float4*)&w[(size_t)(e0 + e) * 32 + k4 * 4];
        ws[e][k4 * 4 + 0] = v.x;
        ws[e][k4 * 4 + 1] = v.y;
        ws[e][k4 * 4 + 2] = v.z;
        ws[e][k4 * 4 + 3] = v.w;
    }
    __syncthreads();
    int j  = tid & 31;       // column
    int eg = tid >> 5;       // warp id -> edge group
    float Bcol[32];
#pragma unroll
    for (int k = 0; k < 32; k++) Bcol[k] = sB[k * 32 + j];
    float sfj = sSf[j];
    for (int ei = 0; ei < 16; ei++) {
        int el = eg * 16 + ei;
        int e = e0 + el;
        float o0 = 0.f, o1 = 0.f;
#pragma unroll
        for (int k = 0; k < 32; k += 2) {
            o0 = fmaf(ws[el][k], Bcol[k], o0);
            o1 = fmaf(ws[el][k + 1], Bcol[k + 1], o1);
        }
        float o = o0 + o1;
        float l = o > 0.f ? o : 0.1f * o;
        float sv = l * sfj;
#pragma unroll
        for (int off = 16; off; off >>= 1) sv += __shfl_xor_sync(0xffffffffu, sv, off);
        if (e < E) {
            g_ow[(size_t)e * 32 + j] = o;
            g_A1[(size_t)e * 32 + j] = sv * ws[el][j];
            sat_out[(size_t)e * 288 + 256 + j] = sv * o;
            if (j == 0) g_s[e] = sv;
        }
    }
}

// ---------------- fuse_gemm: Z=A1@C3 + P1[s]+P2[d]+b; lrelu; @W_attn --------
// also writes sat[:,0:128]=hn[s], sat[:,128:256]=hn[d]; outputs logits, aw.
__global__ __launch_bounds__(256, 2)
void fuse_gemm(const int* __restrict__ src, const int* __restrict__ dst,
               const float* __restrict__ bif, const float* __restrict__ Wattn,
               float* __restrict__ sat_out, int E) {
    __shared__ float As[32][132];
    __shared__ float Bs[32][132];
    __shared__ float part[128][17];
    int tid = threadIdx.x;
    int tx = tid & 15;
    int ty = tid >> 4;
    int row0 = blockIdx.x * 128;

    unsigned long long acc[2][4][2][2];
#pragma unroll
    for (int a = 0; a < 2; a++)
#pragma unroll
        for (int b = 0; b < 4; b++)
#pragma unroll
            for (int c = 0; c < 2; c++)
#pragma unroll
                for (int d = 0; d < 2; d++) acc[a][b][c][d] = 0ull;

#pragma unroll
    for (int i = 0; i < 4; i++) {
        int e = tid + 256 * i;
        int r = e >> 3;
        int kg = e & 7;
        float4 v = make_float4(0.f, 0.f, 0.f, 0.f);
        if (row0 + r < E)
            v = *(const float4*)&g_A1[(size_t)(row0 + r) * 32 + kg * 4];
        As[kg * 4 + 0][r] = v.x;
        As[kg * 4 + 1][r] = v.y;
        As[kg * 4 + 2][r] = v.z;
        As[kg * 4 + 3][r] = v.w;
    }
#pragma unroll
    for (int i = 0; i < 4; i++) {
        int e = tid + 256 * i;
        int k = e >> 5;
        int cg = e & 31;
        *(float4*)&Bs[k][cg * 4] = *(const float4*)&g_C3[k * 128 + cg * 4];
    }
    __syncthreads();
#pragma unroll
    for (int k = 0; k < 32; k++) {
        float4 af0 = *(const float4*)&As[k][ty * 4];
        float4 af1 = *(const float4*)&As[k][64 + ty * 4];
        ulonglong2 b0 = *(const ulonglong2*)&Bs[k][tx * 4];
        ulonglong2 b1 = *(const ulonglong2*)&Bs[k][64 + tx * 4];
        float av[2][4] = {{af0.x, af0.y, af0.z, af0.w}, {af1.x, af1.y, af1.z, af1.w}};
#pragma unroll
        for (int mi = 0; mi < 2; mi++)
#pragma unroll
            for (int j = 0; j < 4; j++) {
                unsigned long long ap = pk2(av[mi][j], av[mi][j]);
                acc[mi][j][0][0] = ffma2(ap, b0.x, acc[mi][j][0][0]);
                acc[mi][j][0][1] = ffma2(ap, b0.y, acc[mi][j][0][1]);
                acc[mi][j][1][0] = ffma2(ap, b1.x, acc[mi][j][1][0]);
                acc[mi][j][1][1] = ffma2(ap, b1.y, acc[mi][j][1][1]);
            }
    }
    __syncthreads();

    // preload per-thread constant cols
    float4 bf0 = *(const float4*)&bif[tx * 4];
    float4 bf1 = *(const float4*)&bif[64 + tx * 4];
    float4 wa0 = *(const float4*)&Wattn[tx * 4];
    float4 wa1 = *(const float4*)&Wattn[64 + tx * 4];

#pragma unroll
    for (int mi = 0; mi < 2; mi++)
#pragma unroll
        for (int j = 0; j < 4; j++) {
            int rl = mi * 64 + ty * 4 + j;
            int row = row0 + rl;
            float partial = 0.f;
            if (row < E) {
                int s = src[row], d = dst[row];
                float4 p1a = *(const float4*)&g_P1[(size_t)s * 128 + tx * 4];
                float4 p2a = *(const float4*)&g_P2[(size_t)d * 128 + tx * 4];
                float4 p1b = *(const float4*)&g_P1[(size_t)s * 128 + 64 + tx * 4];
                float4 p2b = *(const float4*)&g_P2[(size_t)d * 128 + 64 + tx * 4];
                float z[8];
                upk2(z[0], z[1], acc[mi][j][0][0]);
                upk2(z[2], z[3], acc[mi][j][0][1]);
                upk2(z[4], z[5], acc[mi][j][1][0]);
                upk2(z[6], z[7], acc[mi][j][1][1]);
                z[0] += p1a.x + p2a.x + bf0.x;
                z[1] += p1a.y + p2a.y + bf0.y;
                z[2] += p1a.z + p2a.z + bf0.z;
                z[3] += p1a.w + p2a.w + bf0.w;
                z[4] += p1b.x + p2b.x + bf1.x;
                z[5] += p1b.y + p2b.y + bf1.y;
                z[6] += p1b.z + p2b.z + bf1.z;
                z[7] += p1b.w + p2b.w + bf1.w;
                float wv[8] = {wa0.x, wa0.y, wa0.z, wa0.w, wa1.x, wa1.y, wa1.z, wa1.w};
#pragma unroll
                for (int c = 0; c < 8; c++) {
                    float l = z[c] > 0.f ? z[c] : 0.1f * z[c];
                    partial = fmaf(l, wv[c], partial);
                }
                // sat gathers
                size_t so = (size_t)row * 288;
                *(float4*)&sat_out[so + tx * 4]        = *(const float4*)&g_hn[(size_t)s * 128 + tx * 4];
                *(float4*)&sat_out[so + 64 + tx * 4]   = *(const float4*)&g_hn[(size_t)s * 128 + 64 + tx * 4];
                *(float4*)&sat_out[so + 128 + tx * 4]  = *(const float4*)&g_hn[(size_t)d * 128 + tx * 4];
                *(float4*)&sat_out[so + 192 + tx * 4]  = *(const float4*)&g_hn[(size_t)d * 128 + 64 + tx * 4];
            }
            part[rl][tx] = partial;
        }
    __syncthreads();
    if (tid < 128) {
        int row = row0 + tid;
        if (row < E) {
            float v = 0.f;
#pragma unroll
            for (int i = 0; i < 16; i++) v += part[tid][i];
            g_logits[row] = v;
            g_aw[row] = v * g_s[row];
        }
    }
}

// ---------------- segment softmax + aggregate (warp per node) ---------------
__global__ void segment_kernel(const int* __restrict__ src, int Nn) {
    int warp = (blockIdx.x * blockDim.x + threadIdx.x) >> 5;
    int lane = threadIdx.x & 31;
    if (warp >= Nn) return;
    int s0 = g_rowstart[warp], s1 = g_rowstart[warp + 1];
    float acc[5] = {0.f, 0.f, 0.f, 0.f, 0.f};
    if (s1 > s0) {
        float m = -INFINITY;
        for (int e = s0 + lane; e < s1; e += 32) m = fmaxf(m, g_logits[e]);
#pragma unroll
        for (int o = 16; o; o >>= 1) m = fmaxf(m, __shfl_xor_sync(0xffffffffu, m, o));
        float den = 0.f;
        for (int e = s0 + lane; e < s1; e += 32) den += expf(g_logits[e] - m);
#pragma unroll
        for (int o = 16; o; o >>= 1) den += __shfl_xor_sync(0xffffffffu, den, o);
        float inv = 1.0f / den;
        for (int e = s0; e < s1; e++) {
            float alpha = expf(g_logits[e] - m) * inv;
            int sidx = src[e];
#pragma unroll
            for (int i = 0; i < 4; i++)
                acc[i] = fmaf(alpha, g_hn[(size_t)sidx * 128 + lane + 32 * i], acc[i]);
            acc[4] = fmaf(alpha * g_aw[e], g_ow[(size_t)e * 32 + lane], acc[4]);
        }
    }
#pragma unroll
    for (int i = 0; i < 4; i++) g_Acat[(size_t)warp * 288 + lane + 32 * i] = acc[i];
    g_Acat[(size_t)warp * 288 + 128 + lane] = acc[4];
}

__global__ void acat_fill(int Nn) {
    int idx = blockIdx.x * blockDim.x + threadIdx.x;
    if (idx >= Nn * 128) return;
    int r = idx >> 7, c = idx & 127;
    g_Acat[(size_t)r * 288 + 160 + c] = g_hn[idx];
}

__global__ void hnew_fixup(float* __restrict__ hnew, int Nn) {
    int idx = blockIdx.x * blockDim.x + threadIdx.x;
    if (idx >= Nn * 128) return;
    int r = idx >> 7;
    if (g_rowstart[r + 1] == g_rowstart[r]) hnew[idx] = g_hn[idx];
}

// ---------------- wout_gemm: wout = w@C2 + aw*(w@C1) + Q1[s]+Q2[d]+cvec -----
// K=64 in two 32-chunks: chunk0 (A=w, B=C2), chunk1 (A=aw*w, B=C1).
__global__ __launch_bounds__(256, 2)
void wout_gemm(const float* __restrict__ w, const int* __restrict__ src,
               const int* __restrict__ dst, float* __restrict__ wout, int E) {
    __shared__ float As[32][132];
    __shared__ float Bs[32][132];
    __shared__ float saw[128];
    int tid = threadIdx.x;
    int tx = tid & 15;
    int ty = tid >> 4;
    int row0 = blockIdx.x * 128;

    if (tid < 128) saw[tid] = (row0 + tid < E) ? g_aw[row0 + tid] : 0.f;

    unsigned long long acc[2][4][2][2];
#pragma unroll
    for (int a = 0; a < 2; a++)
#pragma unroll
        for (int b = 0; b < 4; b++)
#pragma unroll
            for (int c = 0; c < 2; c++)
#pragma unroll
                for (int d = 0; d < 2; d++) acc[a][b][c][d] = 0ull;

#pragma unroll
    for (int chunk = 0; chunk < 2; chunk++) {
        const float* Bsrc = chunk == 0 ? g_C2 : g_C1;
        if (chunk) __syncthreads();
#pragma unroll
        for (int i = 0; i < 4; i++) {
            int e = tid + 256 * i;
            int r = e >> 3;
            int kg = e & 7;
            float4 v = make_float4(0.f, 0.f, 0.f, 0.f);
            if (row0 + r < E)
                v = *(const float4*)&w[(size_t)(row0 + r) * 32 + kg * 4];
            float sc = chunk == 0 ? 1.f : saw[r];
            As[kg * 4 + 0][r] = sc * v.x;
            As[kg * 4 + 1][r] = sc * v.y;
            As[kg * 4 + 2][r] = sc * v.z;
            As[kg * 4 + 3][r] = sc * v.w;
        }
#pragma unroll
        for (int i = 0; i < 4; i++) {
            int e = tid + 256 * i;
            int k = e >> 5;
            int cg = e & 31;
            *(float4*)&Bs[k][cg * 4] = *(const float4*)&Bsrc[k * 128 + cg * 4];
        }
        __syncthreads();
#pragma unroll
        for (int k = 0; k < 32; k++) {
            float4 af0 = *(const float4*)&As[k][ty * 4];
            float4 af1 = *(const float4*)&As[k][64 + ty * 4];
            ulonglong2 b0 = *(const ulonglong2*)&Bs[k][tx * 4];
            ulonglong2 b1 = *(const ulonglong2*)&Bs[k][64 + tx * 4];
            float av[2][4] = {{af0.x, af0.y, af0.z, af0.w}, {af1.x, af1.y, af1.z, af1.w}};
#pragma unroll
            for (int mi = 0; mi < 2; mi++)
#pragma unroll
                for (int j = 0; j < 4; j++) {
                    unsigned long long ap = pk2(av[mi][j], av[mi][j]);
                    acc[mi][j][0][0] = ffma2(ap, b0.x, acc[mi][j][0][0]);
                    acc[mi][j][0][1] = ffma2(ap, b0.y, acc[mi][j][0][1]);
                    acc[mi][j][1][0] = ffma2(ap, b1.x, acc[mi][j][1][0]);
                    acc[mi][j][1][1] = ffma2(ap, b1.y, acc[mi][j][1][1]);
                }
        }
    }
    // epilogue: + Q1[src]+Q2[dst]+cvec
    float4 cv0 = *(const float4*)&g_cvec[tx * 4];
    float4 cv1 = *(const float4*)&g_cvec[64 + tx * 4];
#pragma unroll
    for (int mi = 0; mi < 2; mi++)
#pragma unroll
        for (int j = 0; j < 4; j++) {
            int row = row0 + mi * 64 + ty * 4 + j;
            if (row < E) {
                int s = src[row], d = dst[row];
                float4 q1a = *(const float4*)&g_Q1[(size_t)s * 128 + tx * 4];
                float4 q2a = *(const float4*)&g_Q2[(size_t)d * 128 + tx * 4];
                float4 q1b = *(const float4*)&g_Q1[(size_t)s * 128 + 64 + tx * 4];
                float4 q2b = *(const float4*)&g_Q2[(size_t)d * 128 + 64 + tx * 4];
                float z[8];
                upk2(z[0], z[1], acc[mi][j][0][0]);
                upk2(z[2], z[3], acc[mi][j][0][1]);
                upk2(z[4], z[5], acc[mi][j][1][0]);
                upk2(z[6], z[7], acc[mi][j][1][1]);
                float4 o0, o1;
                o0.x = z[0] + q1a.x + q2a.x + cv0.x;
                o0.y = z[1] + q1a.y + q2a.y + cv0.y;
                o0.z = z[2] + q1a.z + q2a.z + cv0.z;
                o0.w = z[3] + q1a.w + q2a.w + cv0.w;
                o1.x = z[4] + q1b.x + q2b.x + cv1.x;
                o1.y = z[5] + q1b.y + q2b.y + cv1.y;
                o1.z = z[6] + q1b.z + q2b.z + cv1.z;
                o1.w = z[7] + q1b.w + q2b.w + cv1.w;
                *(float4*)&wout[(size_t)row * 128 + tx * 4] = o0;
                *(float4*)&wout[(size_t)row * 128 + 64 + tx * 4] = o1;
            }
        }
}

// ---------------- launch ----------------
extern "C" void kernel_launch(void* const* d_in, const int* in_sizes, int n_in,
                              void* d_out, int out_size) {
    const float* h        = (const float*)d_in[0];
    const float* w        = (const float*)d_in[1];
    const int*   src      = (const int*)d_in[2];
    const int*   dst      = (const int*)d_in[3];
    const float* W_en     = (const float*)d_in[4];
    const float* W_attn   = (const float*)d_in[5];
    const float* W_if     = (const float*)d_in[6];
    const float* b_if     = (const float*)d_in[7];
    const float* W_ee     = (const float*)d_in[8];
    const float* W_sf     = (const float*)d_in[9];
    const float* W_conc   = (const float*)d_in[10];
    const float* b_conc   = (const float*)d_in[11];
    const float* bn_gamma = (const float*)d_in[12];
    const float* bn_beta  = (const float*)d_in[13];
    const float* bn_mean  = (const float*)d_in[14];
    const float* bn_var   = (const float*)d_in[15];
    const float* W_ag     = (const float*)d_in[16];

    int Nn = in_sizes[0] / 128;
    int E  = in_sizes[2];

    float* out_hnew = (float*)d_out;
    float* out_wout = out_hnew + (size_t)Nn * 128;
    float* out_sat  = out_wout + (size_t)E * 128;

    float *hn_p, *P1_p, *P2_p, *Q1_p, *Q2_p, *Acat_p;
    cudaGetSymbolAddress((void**)&hn_p,   g_hn);
    cudaGetSymbolAddress((void**)&P1_p,   g_P1);
    cudaGetSymbolAddress((void**)&P2_p,   g_P2);
    cudaGetSymbolAddress((void**)&Q1_p,   g_Q1);
    cudaGetSymbolAddress((void**)&Q2_p,   g_Q2);
    cudaGetSymbolAddress((void**)&Acat_p, g_Acat);

    int gbN = (Nn + 127) / 128;
    int gbE = (E + 127) / 128;

    rowstart_kernel<<<(Nn + 256) / 256, 256>>>(dst, E, Nn);
    prep_cmat<<<1, 128>>>(W_if + 256 * 128, W_ag + 256 * 128, W_ee,
                          bn_gamma, bn_beta, bn_mean, bn_var);
    gemm_v3<<<gbN, 256>>>(h, W_en, nullptr, hn_p, Nn, 128);
    k_embed<<<gbE, 256>>>(w, W_ee, W_sf, out_sat, E);
    gemm_v3<<<gbN, 256>>>(hn_p, W_if,             nullptr, P1_p, Nn, 128);
    gemm_v3<<<gbN, 256>>>(hn_p, W_if + 128 * 128, nullptr, P2_p, Nn, 128);
    fuse_gemm<<<gbE, 256>>>(src, dst, b_if, W_attn, out_sat, E);
    segment_kernel<<<(Nn + 7) / 8, 256>>>(src, Nn);
    acat_fill<<<(Nn * 128 + 255) / 256, 256>>>(Nn);
    gemm_v3<<<gbN, 256>>>(Acat_p, W_conc, b_conc, out_hnew, Nn, 288);
    hnew_fixup<<<(Nn * 128 + 255) / 256, 256>>>(out_hnew, Nn);
    gemm_v3<<<gbN, 256>>>(out_hnew, W_ag,             nullptr, Q1_p, Nn, 128);
    gemm_v3<<<gbN, 256>>>(out_hnew, W_ag + 128 * 128, nullptr, Q2_p, Nn, 128);
    wout_gemm<<<gbE, 256>>>(w, src, dst, out_wout, E);
}

// round 6
// speedup vs baseline: 2.3030x; 1.0763x over previous
#include <cuda_runtime.h>
#include <cuda_bf16.h>
#include <math.h>

#define MAXN 50000
#define MAXE 400000

// ---------------- scratch (device globals) ----------------
__device__ float g_hn[MAXN * 128];
__device__ float g_P1[MAXN * 128];
__device__ float g_P2[MAXN * 128];
__device__ float g_Q1[MAXN * 128];
__device__ float g_Q2[MAXN * 128];
__device__ float g_ow[(size_t)MAXE * 32];
__device__ float g_A1[(size_t)MAXE * 32];
__device__ float g_s[MAXE];
__device__ float g_aw[MAXE];
__device__ float g_logits[MAXE];
__device__ float g_Acat[(size_t)MAXN * 288];
__device__ int   g_rowstart[MAXN + 1];
__device__ float g_C1[32 * 128];
__device__ float g_C2[32 * 128];
__device__ float g_C3[32 * 128];
__device__ float g_cvec[128];

// ---------------- f32x2 packed helpers ----------------
__device__ __forceinline__ unsigned long long pk2(float x, float y) {
    unsigned long long r;
    asm("mov.b64 %0, {%1, %2};" : "=l"(r) : "f"(x), "f"(y));
    return r;
}
__device__ __forceinline__ unsigned long long ffma2(unsigned long long a,
                                                    unsigned long long b,
                                                    unsigned long long c) {
    unsigned long long d;
    asm("fma.rn.f32x2 %0, %1, %2, %3;" : "=l"(d) : "l"(a), "l"(b), "l"(c));
    return d;
}
__device__ __forceinline__ unsigned long long fadd2(unsigned long long a,
                                                    unsigned long long b) {
    unsigned long long d;
    asm("add.rn.f32x2 %0, %1, %2;" : "=l"(d) : "l"(a), "l"(b));
    return d;
}
__device__ __forceinline__ void upk2(float& lo, float& hi, unsigned long long v) {
    asm("mov.b64 {%0, %1}, %2;" : "=f"(lo), "=f"(hi) : "l"(v));
}

// ---------------- K0: segment boundaries (dst sorted) ----------------
__global__ void rowstart_kernel(const int* __restrict__ dst, int E, int Nn) {
    int n = blockIdx.x * blockDim.x + threadIdx.x;
    if (n > Nn) return;
    int lo = 0, hi = E;
    while (lo < hi) {
        int mid = (lo + hi) >> 1;
        if (dst[mid] < n) lo = mid + 1; else hi = mid;
    }
    g_rowstart[n] = lo;
}

// ---------------- prep: combined 32x128 matrices + BN fold ----------------
__global__ void prep_cmat(const float* __restrict__ W3,    // W_if rows 256..287
                          const float* __restrict__ Wag3,  // W_ag rows 256..319
                          const float* __restrict__ Wee,   // 32x32
                          const float* __restrict__ gamma, const float* __restrict__ beta,
                          const float* __restrict__ mean,  const float* __restrict__ var) {
    int c = threadIdx.x;  // 128
    __shared__ float sWee[1024];
    __shared__ float ssc[32];
    for (int i = c; i < 1024; i += 128) sWee[i] = Wee[i];
    if (c < 32) ssc[c] = gamma[c] * rsqrtf(var[c] + 1e-5f);
    __syncthreads();
    for (int k = 0; k < 32; k++) {
        float a3 = 0.f, a1 = 0.f, a2 = 0.f;
        for (int j = 0; j < 32; j++) {
            float wk = sWee[k * 32 + j];
            a3 = fmaf(wk, W3[j * 128 + c], a3);
            a1 = fmaf(wk, Wag3[j * 128 + c] * ssc[j], a1);
            a2 = fmaf(wk, Wag3[(32 + j) * 128 + c], a2);
        }
        g_C3[k * 128 + c] = a3;
        g_C1[k * 128 + c] = a1;
        g_C2[k * 128 + c] = a2;
    }
    float cv = 0.f;
    for (int j = 0; j < 32; j++)
        cv = fmaf(beta[j] - mean[j] * ssc[j], Wag3[j * 128 + c], cv);
    g_cvec[c] = cv;
}

// ---------------- gemm_v3: C[M,128] = A[M,K] @ B[K,128] (+bias), f32x2 ------
__global__ __launch_bounds__(256, 2)
void gemm_v3(const float* __restrict__ A, const float* __restrict__ B,
             const float* __restrict__ bias, float* __restrict__ C,
             int M, int K) {
    __shared__ float As[32][132];
    __shared__ float Bs[32][132];
    int tid = threadIdx.x;
    int tx = tid & 15;
    int ty = tid >> 4;
    int row0 = blockIdx.x * 128;

    unsigned long long acc[2][4][2][2];
#pragma unroll
    for (int a = 0; a < 2; a++)
#pragma unroll
        for (int b = 0; b < 4; b++)
#pragma unroll
            for (int c = 0; c < 2; c++)
#pragma unroll
                for (int d = 0; d < 2; d++) acc[a][b][c][d] = 0ull;

    for (int kc = 0; kc < K; kc += 32) {
#pragma unroll
        for (int i = 0; i < 4; i++) {
            int e = tid + 256 * i;
            int r = e >> 3;
            int kg = e & 7;
            float4 v = make_float4(0.f, 0.f, 0.f, 0.f);
            if (row0 + r < M)
                v = *(const float4*)&A[(size_t)(row0 + r) * K + kc + kg * 4];
            As[kg * 4 + 0][r] = v.x;
            As[kg * 4 + 1][r] = v.y;
            As[kg * 4 + 2][r] = v.z;
            As[kg * 4 + 3][r] = v.w;
        }
#pragma unroll
        for (int i = 0; i < 4; i++) {
            int e = tid + 256 * i;
            int k = e >> 5;
            int cg = e & 31;
            *(float4*)&Bs[k][cg * 4] = *(const float4*)&B[(size_t)(kc + k) * 128 + cg * 4];
        }
        __syncthreads();
#pragma unroll
        for (int k = 0; k < 32; k++) {
            float4 af0 = *(const float4*)&As[k][ty * 4];
            float4 af1 = *(const float4*)&As[k][64 + ty * 4];
            ulonglong2 b0 = *(const ulonglong2*)&Bs[k][tx * 4];
            ulonglong2 b1 = *(const ulonglong2*)&Bs[k][64 + tx * 4];
            float av[2][4] = {{af0.x, af0.y, af0.z, af0.w}, {af1.x, af1.y, af1.z, af1.w}};
#pragma unroll
            for (int mi = 0; mi < 2; mi++)
#pragma unroll
                for (int j = 0; j < 4; j++) {
                    unsigned long long ap = pk2(av[mi][j], av[mi][j]);
                    acc[mi][j][0][0] = ffma2(ap, b0.x, acc[mi][j][0][0]);
                    acc[mi][j][0][1] = ffma2(ap, b0.y, acc[mi][j][0][1]);
                    acc[mi][j][1][0] = ffma2(ap, b1.x, acc[mi][j][1][0]);
                    acc[mi][j][1][1] = ffma2(ap, b1.y, acc[mi][j][1][1]);
                }
        }
        __syncthreads();
    }
    ulonglong2 bp0 = {0ull, 0ull}, bp1 = {0ull, 0ull};
    if (bias) {
        bp0 = *(const ulonglong2*)&bias[tx * 4];
        bp1 = *(const ulonglong2*)&bias[64 + tx * 4];
    }
#pragma unroll
    for (int mi = 0; mi < 2; mi++)
#pragma unroll
        for (int j = 0; j < 4; j++) {
            int row = row0 + mi * 64 + ty * 4 + j;
            if (row < M) {
                ulonglong2 o0, o1;
                o0.x = fadd2(acc[mi][j][0][0], bp0.x);
                o0.y = fadd2(acc[mi][j][0][1], bp0.y);
                o1.x = fadd2(acc[mi][j][1][0], bp1.x);
                o1.y = fadd2(acc[mi][j][1][1], bp1.y);
                *(ulonglong2*)&C[(size_t)row * 128 + tx * 4] = o0;
                *(ulonglong2*)&C[(size_t)row * 128 + 64 + tx * 4] = o1;
            }
        }
}

// ---------------- gemm_conc: Acat-gemm with deg==0 fixup in epilogue --------
// hnew = Acat @ W_conc + b; rows with empty segment get hn instead.
__global__ __launch_bounds__(256, 2)
void gemm_conc(const float* __restrict__ A, const float* __restrict__ B,
               const float* __restrict__ bias, float* __restrict__ C,
               int M, int K) {
    __shared__ float As[32][132];
    __shared__ float Bs[32][132];
    int tid = threadIdx.x;
    int tx = tid & 15;
    int ty = tid >> 4;
    int row0 = blockIdx.x * 128;

    unsigned long long acc[2][4][2][2];
#pragma unroll
    for (int a = 0; a < 2; a++)
#pragma unroll
        for (int b = 0; b < 4; b++)
#pragma unroll
            for (int c = 0; c < 2; c++)
#pragma unroll
                for (int d = 0; d < 2; d++) acc[a][b][c][d] = 0ull;

    for (int kc = 0; kc < K; kc += 32) {
#pragma unroll
        for (int i = 0; i < 4; i++) {
            int e = tid + 256 * i;
            int r = e >> 3;
            int kg = e & 7;
            float4 v = make_float4(0.f, 0.f, 0.f, 0.f);
            if (row0 + r < M)
                v = *(const float4*)&A[(size_t)(row0 + r) * K + kc + kg * 4];
            As[kg * 4 + 0][r] = v.x;
            As[kg * 4 + 1][r] = v.y;
            As[kg * 4 + 2][r] = v.z;
            As[kg * 4 + 3][r] = v.w;
        }
#pragma unroll
        for (int i = 0; i < 4; i++) {
            int e = tid + 256 * i;
            int k = e >> 5;
            int cg = e & 31;
            *(float4*)&Bs[k][cg * 4] = *(const float4*)&B[(size_t)(kc + k) * 128 + cg * 4];
        }
        __syncthreads();
#pragma unroll
        for (int k = 0; k < 32; k++) {
            float4 af0 = *(const float4*)&As[k][ty * 4];
            float4 af1 = *(const float4*)&As[k][64 + ty * 4];
            ulonglong2 b0 = *(const ulonglong2*)&Bs[k][tx * 4];
            ulonglong2 b1 = *(const ulonglong2*)&Bs[k][64 + tx * 4];
            float av[2][4] = {{af0.x, af0.y, af0.z, af0.w}, {af1.x, af1.y, af1.z, af1.w}};
#pragma unroll
            for (int mi = 0; mi < 2; mi++)
#pragma unroll
                for (int j = 0; j < 4; j++) {
                    unsigned long long ap = pk2(av[mi][j], av[mi][j]);
                    acc[mi][j][0][0] = ffma2(ap, b0.x, acc[mi][j][0][0]);
                    acc[mi][j][0][1] = ffma2(ap, b0.y, acc[mi][j][0][1]);
                    acc[mi][j][1][0] = ffma2(ap, b1.x, acc[mi][j][1][0]);
                    acc[mi][j][1][1] = ffma2(ap, b1.y, acc[mi][j][1][1]);
                }
        }
        __syncthreads();
    }
    ulonglong2 bp0 = *(const ulonglong2*)&bias[tx * 4];
    ulonglong2 bp1 = *(const ulonglong2*)&bias[64 + tx * 4];
#pragma unroll
    for (int mi = 0; mi < 2; mi++)
#pragma unroll
        for (int j = 0; j < 4; j++) {
            int row = row0 + mi * 64 + ty * 4 + j;
            if (row < M) {
                ulonglong2 o0, o1;
                if (g_rowstart[row + 1] == g_rowstart[row]) {
                    o0 = *(const ulonglong2*)&g_hn[(size_t)row * 128 + tx * 4];
                    o1 = *(const ulonglong2*)&g_hn[(size_t)row * 128 + 64 + tx * 4];
                } else {
                    o0.x = fadd2(acc[mi][j][0][0], bp0.x);
                    o0.y = fadd2(acc[mi][j][0][1], bp0.y);
                    o1.x = fadd2(acc[mi][j][1][0], bp1.x);
                    o1.y = fadd2(acc[mi][j][1][1], bp1.y);
                }
                *(ulonglong2*)&C[(size_t)row * 128 + tx * 4] = o0;
                *(ulonglong2*)&C[(size_t)row * 128 + 64 + tx * 4] = o1;
            }
        }
}

// ---------------- k_embed_v2: GEMM-style. ow, s, A1=s*w, sat[:,256:288] -----
// Block: 256 edges x 32 cols, 256 threads. Thread: 4 edges x 8 cols (f32x2).
__global__ __launch_bounds__(256)
void k_embed_v2(const float* __restrict__ w, const float* __restrict__ Wee,
                const float* __restrict__ Wsf, float* __restrict__ sat_out, int E) {
    __shared__ float As[32][260];   // [k][edge], transposed
    __shared__ float Bs[32][40];    // [j][c], padded to 160B rows (16B-aligned)
    __shared__ float sSf[32];
    int tid = threadIdx.x;
    int e0 = blockIdx.x * 256;

    {
        int j = tid >> 3, c4 = tid & 7;
        *(float4*)&Bs[j][c4 * 4] = *(const float4*)&Wee[j * 32 + c4 * 4];
    }
    if (tid < 32) sSf[tid] = Wsf[tid];
#pragma unroll
    for (int i = 0; i < 8; i++) {
        int idx = tid + 256 * i;      // 0..2047 float4 units
        int r = idx >> 3, kg = idx & 7;
        float4 v = make_float4(0.f, 0.f, 0.f, 0.f);
        if (e0 + r < E) v = *(const float4*)&w[(size_t)(e0 + r) * 32 + kg * 4];
        As[kg * 4 + 0][r] = v.x;
        As[kg * 4 + 1][r] = v.y;
        As[kg * 4 + 2][r] = v.z;
        As[kg * 4 + 3][r] = v.w;
    }
    __syncthreads();

    int tx = tid & 3;        // col group: cols [tx*8, tx*8+8)
    int ty = tid >> 2;       // row group: edges [ty*4, ty*4+4)
    unsigned long long acc[4][4];
#pragma unroll
    for (int r = 0; r < 4; r++)
#pragma unroll
        for (int c = 0; c < 4; c++) acc[r][c] = 0ull;

#pragma unroll
    for (int k = 0; k < 32; k++) {
        float4 a = *(const float4*)&As[k][ty * 4];
        ulonglong2 b01 = *(const ulonglong2*)&Bs[k][tx * 8];
        ulonglong2 b23 = *(const ulonglong2*)&Bs[k][tx * 8 + 4];
        float av[4] = {a.x, a.y, a.z, a.w};
#pragma unroll
        for (int r = 0; r < 4; r++) {
            unsigned long long ap = pk2(av[r], av[r]);
            acc[r][0] = ffma2(ap, b01.x, acc[r][0]);
            acc[r][1] = ffma2(ap, b01.y, acc[r][1]);
            acc[r][2] = ffma2(ap, b23.x, acc[r][2]);
            acc[r][3] = ffma2(ap, b23.y, acc[r][3]);
        }
    }

    float sf[8];
#pragma unroll
    for (int c = 0; c < 8; c++) sf[c] = sSf[tx * 8 + c];

#pragma unroll
    for (int r = 0; r < 4; r++) {
        float o[8];
        upk2(o[0], o[1], acc[r][0]);
        upk2(o[2], o[3], acc[r][1]);
        upk2(o[4], o[5], acc[r][2]);
        upk2(o[6], o[7], acc[r][3]);
        float partial = 0.f;
#pragma unroll
        for (int c = 0; c < 8; c++) {
            float l = o[c] > 0.f ? o[c] : 0.1f * o[c];
            partial = fmaf(l, sf[c], partial);
        }
        partial += __shfl_xor_sync(0xffffffffu, partial, 1);
        partial += __shfl_xor_sync(0xffffffffu, partial, 2);
        float s = partial;     // full row-sum in all 4 tx lanes
        int el = ty * 4 + r;
        int e = e0 + el;
        if (e < E) {
            float4 o0 = make_float4(o[0], o[1], o[2], o[3]);
            float4 o1 = make_float4(o[4], o[5], o[6], o[7]);
            *(float4*)&g_ow[(size_t)e * 32 + tx * 8]     = o0;
            *(float4*)&g_ow[(size_t)e * 32 + tx * 8 + 4] = o1;
            float4 so0 = make_float4(s * o[0], s * o[1], s * o[2], s * o[3]);
            float4 so1 = make_float4(s * o[4], s * o[5], s * o[6], s * o[7]);
            *(float4*)&sat_out[(size_t)e * 288 + 256 + tx * 8]     = so0;
            *(float4*)&sat_out[(size_t)e * 288 + 256 + tx * 8 + 4] = so1;
            float4 a10, a11;
            a10.x = s * As[tx * 8 + 0][el];
            a10.y = s * As[tx * 8 + 1][el];
            a10.z = s * As[tx * 8 + 2][el];
            a10.w = s * As[tx * 8 + 3][el];
            a11.x = s * As[tx * 8 + 4][el];
            a11.y = s * As[tx * 8 + 5][el];
            a11.z = s * As[tx * 8 + 6][el];
            a11.w = s * As[tx * 8 + 7][el];
            *(float4*)&g_A1[(size_t)e * 32 + tx * 8]     = a10;
            *(float4*)&g_A1[(size_t)e * 32 + tx * 8 + 4] = a11;
            if (tx == 0) g_s[e] = s;
        }
    }
}

// ---------------- fuse_gemm: Z=A1@C3 + P1[s]+P2[d]+b; lrelu; @W_attn --------
__global__ __launch_bounds__(256, 2)
void fuse_gemm(const int* __restrict__ src, const int* __restrict__ dst,
               const float* __restrict__ bif, const float* __restrict__ Wattn,
               float* __restrict__ sat_out, int E) {
    __shared__ float As[32][132];
    __shared__ float Bs[32][132];
    __shared__ float part[128][17];
    int tid = threadIdx.x;
    int tx = tid & 15;
    int ty = tid >> 4;
    int row0 = blockIdx.x * 128;

    unsigned long long acc[2][4][2][2];
#pragma unroll
    for (int a = 0; a < 2; a++)
#pragma unroll
        for (int b = 0; b < 4; b++)
#pragma unroll
            for (int c = 0; c < 2; c++)
#pragma unroll
                for (int d = 0; d < 2; d++) acc[a][b][c][d] = 0ull;

#pragma unroll
    for (int i = 0; i < 4; i++) {
        int e = tid + 256 * i;
        int r = e >> 3;
        int kg = e & 7;
        float4 v = make_float4(0.f, 0.f, 0.f, 0.f);
        if (row0 + r < E)
            v = *(const float4*)&g_A1[(size_t)(row0 + r) * 32 + kg * 4];
        As[kg * 4 + 0][r] = v.x;
        As[kg * 4 + 1][r] = v.y;
        As[kg * 4 + 2][r] = v.z;
        As[kg * 4 + 3][r] = v.w;
    }
#pragma unroll
    for (int i = 0; i < 4; i++) {
        int e = tid + 256 * i;
        int k = e >> 5;
        int cg = e & 31;
        *(float4*)&Bs[k][cg * 4] = *(const float4*)&g_C3[k * 128 + cg * 4];
    }
    __syncthreads();
#pragma unroll
    for (int k = 0; k < 32; k++) {
        float4 af0 = *(const float4*)&As[k][ty * 4];
        float4 af1 = *(const float4*)&As[k][64 + ty * 4];
        ulonglong2 b0 = *(const ulonglong2*)&Bs[k][tx * 4];
        ulonglong2 b1 = *(const ulonglong2*)&Bs[k][64 + tx * 4];
        float av[2][4] = {{af0.x, af0.y, af0.z, af0.w}, {af1.x, af1.y, af1.z, af1.w}};
#pragma unroll
        for (int mi = 0; mi < 2; mi++)
#pragma unroll
            for (int j = 0; j < 4; j++) {
                unsigned long long ap = pk2(av[mi][j], av[mi][j]);
                acc[mi][j][0][0] = ffma2(ap, b0.x, acc[mi][j][0][0]);
                acc[mi][j][0][1] = ffma2(ap, b0.y, acc[mi][j][0][1]);
                acc[mi][j][1][0] = ffma2(ap, b1.x, acc[mi][j][1][0]);
                acc[mi][j][1][1] = ffma2(ap, b1.y, acc[mi][j][1][1]);
            }
    }
    __syncthreads();

    float4 bf0 = *(const float4*)&bif[tx * 4];
    float4 bf1 = *(const float4*)&bif[64 + tx * 4];
    float4 wa0 = *(const float4*)&Wattn[tx * 4];
    float4 wa1 = *(const float4*)&Wattn[64 + tx * 4];

#pragma unroll
    for (int mi = 0; mi < 2; mi++)
#pragma unroll
        for (int j = 0; j < 4; j++) {
            int rl = mi * 64 + ty * 4 + j;
            int row = row0 + rl;
            float partial = 0.f;
            if (row < E) {
                int s = src[row], d = dst[row];
                float4 p1a = *(const float4*)&g_P1[(size_t)s * 128 + tx * 4];
                float4 p2a = *(const float4*)&g_P2[(size_t)d * 128 + tx * 4];
                float4 p1b = *(const float4*)&g_P1[(size_t)s * 128 + 64 + tx * 4];
                float4 p2b = *(const float4*)&g_P2[(size_t)d * 128 + 64 + tx * 4];
                float z[8];
                upk2(z[0], z[1], acc[mi][j][0][0]);
                upk2(z[2], z[3], acc[mi][j][0][1]);
                upk2(z[4], z[5], acc[mi][j][1][0]);
                upk2(z[6], z[7], acc[mi][j][1][1]);
                z[0] += p1a.x + p2a.x + bf0.x;
                z[1] += p1a.y + p2a.y + bf0.y;
                z[2] += p1a.z + p2a.z + bf0.z;
                z[3] += p1a.w + p2a.w + bf0.w;
                z[4] += p1b.x + p2b.x + bf1.x;
                z[5] += p1b.y + p2b.y + bf1.y;
                z[6] += p1b.z + p2b.z + bf1.z;
                z[7] += p1b.w + p2b.w + bf1.w;
                float wv[8] = {wa0.x, wa0.y, wa0.z, wa0.w, wa1.x, wa1.y, wa1.z, wa1.w};
#pragma unroll
                for (int c = 0; c < 8; c++) {
                    float l = z[c] > 0.f ? z[c] : 0.1f * z[c];
                    partial = fmaf(l, wv[c], partial);
                }
                size_t so = (size_t)row * 288;
                *(float4*)&sat_out[so + tx * 4]        = *(const float4*)&g_hn[(size_t)s * 128 + tx * 4];
                *(float4*)&sat_out[so + 64 + tx * 4]   = *(const float4*)&g_hn[(size_t)s * 128 + 64 + tx * 4];
                *(float4*)&sat_out[so + 128 + tx * 4]  = *(const float4*)&g_hn[(size_t)d * 128 + tx * 4];
                *(float4*)&sat_out[so + 192 + tx * 4]  = *(const float4*)&g_hn[(size_t)d * 128 + 64 + tx * 4];
            }
            part[rl][tx] = partial;
        }
    __syncthreads();
    if (tid < 128) {
        int row = row0 + tid;
        if (row < E) {
            float v = 0.f;
#pragma unroll
            for (int i = 0; i < 16; i++) v += part[tid][i];
            g_logits[row] = v;
            g_aw[row] = v * g_s[row];
        }
    }
}

// ---------------- segment softmax + aggregate + hn copy (warp per node) -----
__global__ void segment_kernel(const int* __restrict__ src, int Nn) {
    int warp = (blockIdx.x * blockDim.x + threadIdx.x) >> 5;
    int lane = threadIdx.x & 31;
    if (warp >= Nn) return;
    int s0 = g_rowstart[warp], s1 = g_rowstart[warp + 1];
    float acc[5] = {0.f, 0.f, 0.f, 0.f, 0.f};
    if (s1 > s0) {
        float m = -INFINITY;
        for (int e = s0 + lane; e < s1; e += 32) m = fmaxf(m, g_logits[e]);
#pragma unroll
        for (int o = 16; o; o >>= 1) m = fmaxf(m, __shfl_xor_sync(0xffffffffu, m, o));
        float den = 0.f;
        for (int e = s0 + lane; e < s1; e += 32) den += expf(g_logits[e] - m);
#pragma unroll
        for (int o = 16; o; o >>= 1) den += __shfl_xor_sync(0xffffffffu, den, o);
        float inv = 1.0f / den;
        for (int e = s0; e < s1; e++) {
            float alpha = expf(g_logits[e] - m) * inv;
            int sidx = src[e];
#pragma unroll
            for (int i = 0; i < 4; i++)
                acc[i] = fmaf(alpha, g_hn[(size_t)sidx * 128 + lane + 32 * i], acc[i]);
            acc[4] = fmaf(alpha * g_aw[e], g_ow[(size_t)e * 32 + lane], acc[4]);
        }
    }
#pragma unroll
    for (int i = 0; i < 4; i++) g_Acat[(size_t)warp * 288 + lane + 32 * i] = acc[i];
    g_Acat[(size_t)warp * 288 + 128 + lane] = acc[4];
    // fill Acat[:,160:288] = hn (one float4 per lane)
    float4 hv = *(const float4*)&g_hn[(size_t)warp * 128 + lane * 4];
    *(float4*)&g_Acat[(size_t)warp * 288 + 160 + lane * 4] = hv;
}

// ---------------- wout_gemm: wout = w@C2 + aw*(w@C1) + Q1[s]+Q2[d]+cvec -----
__global__ __launch_bounds__(256, 2)
void wout_gemm(const float* __restrict__ w, const int* __restrict__ src,
               const int* __restrict__ dst, float* __restrict__ wout, int E) {
    __shared__ float As[32][132];
    __shared__ float Bs[32][132];
    __shared__ float saw[128];
    int tid = threadIdx.x;
    int tx = tid & 15;
    int ty = tid >> 4;
    int row0 = blockIdx.x * 128;

    if (tid < 128) saw[tid] = (row0 + tid < E) ? g_aw[row0 + tid] : 0.f;

    unsigned long long acc[2][4][2][2];
#pragma unroll
    for (int a = 0; a < 2; a++)
#pragma unroll
        for (int b = 0; b < 4; b++)
#pragma unroll
            for (int c = 0; c < 2; c++)
#pragma unroll
                for (int d = 0; d < 2; d++) acc[a][b][c][d] = 0ull;

#pragma unroll
    for (int chunk = 0; chunk < 2; chunk++) {
        const float* Bsrc = chunk == 0 ? g_C2 : g_C1;
        if (chunk) __syncthreads();
#pragma unroll
        for (int i = 0; i < 4; i++) {
            int e = tid + 256 * i;
            int r = e >> 3;
            int kg = e & 7;
            float4 v = make_float4(0.f, 0.f, 0.f, 0.f);
            if (row0 + r < E)
                v = *(const float4*)&w[(size_t)(row0 + r) * 32 + kg * 4];
            float sc = chunk == 0 ? 1.f : saw[r];
            As[kg * 4 + 0][r] = sc * v.x;
            As[kg * 4 + 1][r] = sc * v.y;
            As[kg * 4 + 2][r] = sc * v.z;
            As[kg * 4 + 3][r] = sc * v.w;
        }
#pragma unroll
        for (int i = 0; i < 4; i++) {
            int e = tid + 256 * i;
            int k = e >> 5;
            int cg = e & 31;
            *(float4*)&Bs[k][cg * 4] = *(const float4*)&Bsrc[k * 128 + cg * 4];
        }
        __syncthreads();
#pragma unroll
        for (int k = 0; k < 32; k++) {
            float4 af0 = *(const float4*)&As[k][ty * 4];
            float4 af1 = *(const float4*)&As[k][64 + ty * 4];
            ulonglong2 b0 = *(const ulonglong2*)&Bs[k][tx * 4];
            ulonglong2 b1 = *(const ulonglong2*)&Bs[k][64 + tx * 4];
            float av[2][4] = {{af0.x, af0.y, af0.z, af0.w}, {af1.x, af1.y, af1.z, af1.w}};
#pragma unroll
            for (int mi = 0; mi < 2; mi++)
#pragma unroll
                for (int j = 0; j < 4; j++) {
                    unsigned long long ap = pk2(av[mi][j], av[mi][j]);
                    acc[mi][j][0][0] = ffma2(ap, b0.x, acc[mi][j][0][0]);
                    acc[mi][j][0][1] = ffma2(ap, b0.y, acc[mi][j][0][1]);
                    acc[mi][j][1][0] = ffma2(ap, b1.x, acc[mi][j][1][0]);
                    acc[mi][j][1][1] = ffma2(ap, b1.y, acc[mi][j][1][1]);
                }
        }
    }
    float4 cv0 = *(const float4*)&g_cvec[tx * 4];
    float4 cv1 = *(const float4*)&g_cvec[64 + tx * 4];
#pragma unroll
    for (int mi = 0; mi < 2; mi++)
#pragma unroll
        for (int j = 0; j < 4; j++) {
            int row = row0 + mi * 64 + ty * 4 + j;
            if (row < E) {
                int s = src[row], d = dst[row];
                float4 q1a = *(const float4*)&g_Q1[(size_t)s * 128 + tx * 4];
                float4 q2a = *(const float4*)&g_Q2[(size_t)d * 128 + tx * 4];
                float4 q1b = *(const float4*)&g_Q1[(size_t)s * 128 + 64 + tx * 4];
                float4 q2b = *(const float4*)&g_Q2[(size_t)d * 128 + 64 + tx * 4];
                float z[8];
                upk2(z[0], z[1], acc[mi][j][0][0]);
                upk2(z[2], z[3], acc[mi][j][0][1]);
                upk2(z[4], z[5], acc[mi][j][1][0]);
                upk2(z[6], z[7], acc[mi][j][1][1]);
                float4 o0, o1;
                o0.x = z[0] + q1a.x + q2a.x + cv0.x;
                o0.y = z[1] + q1a.y + q2a.y + cv0.y;
                o0.z = z[2] + q1a.z + q2a.z + cv0.z;
                o0.w = z[3] + q1a.w + q2a.w + cv0.w;
                o1.x = z[4] + q1b.x + q2b.x + cv1.x;
                o1.y = z[5] + q1b.y + q2b.y + cv1.y;
                o1.z = z[6] + q1b.z + q2b.z + cv1.z;
                o1.w = z[7] + q1b.w + q2b.w + cv1.w;
                *(float4*)&wout[(size_t)row * 128 + tx * 4] = o0;
                *(float4*)&wout[(size_t)row * 128 + 64 + tx * 4] = o1;
            }
        }
}

// ---------------- launch ----------------
extern "C" void kernel_launch(void* const* d_in, const int* in_sizes, int n_in,
                              void* d_out, int out_size) {
    const float* h        = (const float*)d_in[0];
    const float* w        = (const float*)d_in[1];
    const int*   src      = (const int*)d_in[2];
    const int*   dst      = (const int*)d_in[3];
    const float* W_en     = (const float*)d_in[4];
    const float* W_attn   = (const float*)d_in[5];
    const float* W_if     = (const float*)d_in[6];
    const float* b_if     = (const float*)d_in[7];
    const float* W_ee     = (const float*)d_in[8];
    const float* W_sf     = (const float*)d_in[9];
    const float* W_conc   = (const float*)d_in[10];
    const float* b_conc   = (const float*)d_in[11];
    const float* bn_gamma = (const float*)d_in[12];
    const float* bn_beta  = (const float*)d_in[13];
    const float* bn_mean  = (const float*)d_in[14];
    const float* bn_var   = (const float*)d_in[15];
    const float* W_ag     = (const float*)d_in[16];

    int Nn = in_sizes[0] / 128;
    int E  = in_sizes[2];

    float* out_hnew = (float*)d_out;
    float* out_wout = out_hnew + (size_t)Nn * 128;
    float* out_sat  = out_wout + (size_t)E * 128;

    float *hn_p, *P1_p, *P2_p, *Q1_p, *Q2_p, *Acat_p;
    cudaGetSymbolAddress((void**)&hn_p,   g_hn);
    cudaGetSymbolAddress((void**)&P1_p,   g_P1);
    cudaGetSymbolAddress((void**)&P2_p,   g_P2);
    cudaGetSymbolAddress((void**)&Q1_p,   g_Q1);
    cudaGetSymbolAddress((void**)&Q2_p,   g_Q2);
    cudaGetSymbolAddress((void**)&Acat_p, g_Acat);

    int gbN = (Nn + 127) / 128;
    int gbE = (E + 127) / 128;
    int gbE2 = (E + 255) / 256;

    rowstart_kernel<<<(Nn + 256) / 256, 256>>>(dst, E, Nn);
    prep_cmat<<<1, 128>>>(W_if + 256 * 128, W_ag + 256 * 128, W_ee,
                          bn_gamma, bn_beta, bn_mean, bn_var);
    gemm_v3<<<gbN, 256>>>(h, W_en, nullptr, hn_p, Nn, 128);
    k_embed_v2<<<gbE2, 256>>>(w, W_ee, W_sf, out_sat, E);
    gemm_v3<<<gbN, 256>>>(hn_p, W_if,             nullptr, P1_p, Nn, 128);
    gemm_v3<<<gbN, 256>>>(hn_p, W_if + 128 * 128, nullptr, P2_p, Nn, 128);
    fuse_gemm<<<gbE, 256>>>(src, dst, b_if, W_attn, out_sat, E);
    segment_kernel<<<(Nn + 7) / 8, 256>>>(src, Nn);
    gemm_conc<<<gbN, 256>>>(Acat_p, W_conc, b_conc, out_hnew, Nn, 288);
    gemm_v3<<<gbN, 256>>>(out_hnew, W_ag,             nullptr, Q1_p, Nn, 128);
    gemm_v3<<<gbN, 256>>>(out_hnew, W_ag + 128 * 128, nullptr, Q2_p, Nn, 128);
    wout_gemm<<<gbE, 256>>>(w, src, dst, out_wout, E);
}

// round 7
// speedup vs baseline: 2.4612x; 1.0687x over previous
#include <cuda_runtime.h>
#include <cuda_bf16.h>
#include <math.h>

#define MAXN 50000
#define MAXE 400000

// ---------------- scratch (device globals) ----------------
__device__ float g_hn[MAXN * 128];
__device__ float g_P1[MAXN * 128];
__device__ float g_P2[MAXN * 128];
__device__ float g_Q1[MAXN * 128];
__device__ float g_Q2[MAXN * 128];
__device__ float g_ow[(size_t)MAXE * 32];
__device__ float g_aw[MAXE];
__device__ float g_logits[MAXE];
__device__ float g_Acat[(size_t)MAXN * 288];
__device__ int   g_rowstart[MAXN + 1];
__device__ float g_C1[32 * 128];
__device__ float g_C2[32 * 128];
__device__ float g_C3[32 * 128];
__device__ float g_cvec[128];

// ---------------- f32x2 packed helpers ----------------
__device__ __forceinline__ unsigned long long pk2(float x, float y) {
    unsigned long long r;
    asm("mov.b64 %0, {%1, %2};" : "=l"(r) : "f"(x), "f"(y));
    return r;
}
__device__ __forceinline__ unsigned long long ffma2(unsigned long long a,
                                                    unsigned long long b,
                                                    unsigned long long c) {
    unsigned long long d;
    asm("fma.rn.f32x2 %0, %1, %2, %3;" : "=l"(d) : "l"(a), "l"(b), "l"(c));
    return d;
}
__device__ __forceinline__ unsigned long long fadd2(unsigned long long a,
                                                    unsigned long long b) {
    unsigned long long d;
    asm("add.rn.f32x2 %0, %1, %2;" : "=l"(d) : "l"(a), "l"(b));
    return d;
}
__device__ __forceinline__ void upk2(float& lo, float& hi, unsigned long long v) {
    asm("mov.b64 {%0, %1}, %2;" : "=f"(lo), "=f"(hi) : "l"(v));
}

// ---------------- K0: segment boundaries (dst sorted) ----------------
__global__ void rowstart_kernel(const int* __restrict__ dst, int E, int Nn) {
    int n = blockIdx.x * blockDim.x + threadIdx.x;
    if (n > Nn) return;
    int lo = 0, hi = E;
    while (lo < hi) {
        int mid = (lo + hi) >> 1;
        if (dst[mid] < n) lo = mid + 1; else hi = mid;
    }
    g_rowstart[n] = lo;
}

// ---------------- prep: combined 32x128 matrices + BN fold ----------------
__global__ void prep_cmat(const float* __restrict__ W3,    // W_if rows 256..287
                          const float* __restrict__ Wag3,  // W_ag rows 256..319
                          const float* __restrict__ Wee,   // 32x32
                          const float* __restrict__ gamma, const float* __restrict__ beta,
                          const float* __restrict__ mean,  const float* __restrict__ var) {
    int c = threadIdx.x;  // 128
    __shared__ float sWee[1024];
    __shared__ float ssc[32];
    for (int i = c; i < 1024; i += 128) sWee[i] = Wee[i];
    if (c < 32) ssc[c] = gamma[c] * rsqrtf(var[c] + 1e-5f);
    __syncthreads();
    for (int k = 0; k < 32; k++) {
        float a3 = 0.f, a1 = 0.f, a2 = 0.f;
        for (int j = 0; j < 32; j++) {
            float wk = sWee[k * 32 + j];
            a3 = fmaf(wk, W3[j * 128 + c], a3);
            a1 = fmaf(wk, Wag3[j * 128 + c] * ssc[j], a1);
            a2 = fmaf(wk, Wag3[(32 + j) * 128 + c], a2);
        }
        g_C3[k * 128 + c] = a3;
        g_C1[k * 128 + c] = a1;
        g_C2[k * 128 + c] = a2;
    }
    float cv = 0.f;
    for (int j = 0; j < 32; j++)
        cv = fmaf(beta[j] - mean[j] * ssc[j], Wag3[j * 128 + c], cv);
    g_cvec[c] = cv;
}

// ---------------- gemm_v3: C[M,128] = A[M,K] @ B[K,128] (+bias), f32x2 ------
__global__ __launch_bounds__(256, 2)
void gemm_v3(const float* __restrict__ A, const float* __restrict__ B,
             const float* __restrict__ bias, float* __restrict__ C,
             int M, int K) {
    __shared__ float As[32][132];
    __shared__ float Bs[32][132];
    int tid = threadIdx.x;
    int tx = tid & 15;
    int ty = tid >> 4;
    int row0 = blockIdx.x * 128;

    unsigned long long acc[2][4][2][2];
#pragma unroll
    for (int a = 0; a < 2; a++)
#pragma unroll
        for (int b = 0; b < 4; b++)
#pragma unroll
            for (int c = 0; c < 2; c++)
#pragma unroll
                for (int d = 0; d < 2; d++) acc[a][b][c][d] = 0ull;

    for (int kc = 0; kc < K; kc += 32) {
#pragma unroll
        for (int i = 0; i < 4; i++) {
            int e = tid + 256 * i;
            int r = e >> 3;
            int kg = e & 7;
            float4 v = make_float4(0.f, 0.f, 0.f, 0.f);
            if (row0 + r < M)
                v = *(const float4*)&A[(size_t)(row0 + r) * K + kc + kg * 4];
            As[kg * 4 + 0][r] = v.x;
            As[kg * 4 + 1][r] = v.y;
            As[kg * 4 + 2][r] = v.z;
            As[kg * 4 + 3][r] = v.w;
        }
#pragma unroll
        for (int i = 0; i < 4; i++) {
            int e = tid + 256 * i;
            int k = e >> 5;
            int cg = e & 31;
            *(float4*)&Bs[k][cg * 4] = *(const float4*)&B[(size_t)(kc + k) * 128 + cg * 4];
        }
        __syncthreads();
#pragma unroll
        for (int k = 0; k < 32; k++) {
            float4 af0 = *(const float4*)&As[k][ty * 4];
            float4 af1 = *(const float4*)&As[k][64 + ty * 4];
            ulonglong2 b0 = *(const ulonglong2*)&Bs[k][tx * 4];
            ulonglong2 b1 = *(const ulonglong2*)&Bs[k][64 + tx * 4];
            float av[2][4] = {{af0.x, af0.y, af0.z, af0.w}, {af1.x, af1.y, af1.z, af1.w}};
#pragma unroll
            for (int mi = 0; mi < 2; mi++)
#pragma unroll
                for (int j = 0; j < 4; j++) {
                    unsigned long long ap = pk2(av[mi][j], av[mi][j]);
                    acc[mi][j][0][0] = ffma2(ap, b0.x, acc[mi][j][0][0]);
                    acc[mi][j][0][1] = ffma2(ap, b0.y, acc[mi][j][0][1]);
                    acc[mi][j][1][0] = ffma2(ap, b1.x, acc[mi][j][1][0]);
                    acc[mi][j][1][1] = ffma2(ap, b1.y, acc[mi][j][1][1]);
                }
        }
        __syncthreads();
    }
    ulonglong2 bp0 = {0ull, 0ull}, bp1 = {0ull, 0ull};
    if (bias) {
        bp0 = *(const ulonglong2*)&bias[tx * 4];
        bp1 = *(const ulonglong2*)&bias[64 + tx * 4];
    }
#pragma unroll
    for (int mi = 0; mi < 2; mi++)
#pragma unroll
        for (int j = 0; j < 4; j++) {
            int row = row0 + mi * 64 + ty * 4 + j;
            if (row < M) {
                ulonglong2 o0, o1;
                o0.x = fadd2(acc[mi][j][0][0], bp0.x);
                o0.y = fadd2(acc[mi][j][0][1], bp0.y);
                o1.x = fadd2(acc[mi][j][1][0], bp1.x);
                o1.y = fadd2(acc[mi][j][1][1], bp1.y);
                *(ulonglong2*)&C[(size_t)row * 128 + tx * 4] = o0;
                *(ulonglong2*)&C[(size_t)row * 128 + 64 + tx * 4] = o1;
            }
        }
}

// ---------------- gemm_conc: Acat-gemm with deg==0 fixup in epilogue --------
__global__ __launch_bounds__(256, 2)
void gemm_conc(const float* __restrict__ A, const float* __restrict__ B,
               const float* __restrict__ bias, float* __restrict__ C,
               int M, int K) {
    __shared__ float As[32][132];
    __shared__ float Bs[32][132];
    int tid = threadIdx.x;
    int tx = tid & 15;
    int ty = tid >> 4;
    int row0 = blockIdx.x * 128;

    unsigned long long acc[2][4][2][2];
#pragma unroll
    for (int a = 0; a < 2; a++)
#pragma unroll
        for (int b = 0; b < 4; b++)
#pragma unroll
            for (int c = 0; c < 2; c++)
#pragma unroll
                for (int d = 0; d < 2; d++) acc[a][b][c][d] = 0ull;

    for (int kc = 0; kc < K; kc += 32) {
#pragma unroll
        for (int i = 0; i < 4; i++) {
            int e = tid + 256 * i;
            int r = e >> 3;
            int kg = e & 7;
            float4 v = make_float4(0.f, 0.f, 0.f, 0.f);
            if (row0 + r < M)
                v = *(const float4*)&A[(size_t)(row0 + r) * K + kc + kg * 4];
            As[kg * 4 + 0][r] = v.x;
            As[kg * 4 + 1][r] = v.y;
            As[kg * 4 + 2][r] = v.z;
            As[kg * 4 + 3][r] = v.w;
        }
#pragma unroll
        for (int i = 0; i < 4; i++) {
            int e = tid + 256 * i;
            int k = e >> 5;
            int cg = e & 31;
            *(float4*)&Bs[k][cg * 4] = *(const float4*)&B[(size_t)(kc + k) * 128 + cg * 4];
        }
        __syncthreads();
#pragma unroll
        for (int k = 0; k < 32; k++) {
            float4 af0 = *(const float4*)&As[k][ty * 4];
            float4 af1 = *(const float4*)&As[k][64 + ty * 4];
            ulonglong2 b0 = *(const ulonglong2*)&Bs[k][tx * 4];
            ulonglong2 b1 = *(const ulonglong2*)&Bs[k][64 + tx * 4];
            float av[2][4] = {{af0.x, af0.y, af0.z, af0.w}, {af1.x, af1.y, af1.z, af1.w}};
#pragma unroll
            for (int mi = 0; mi < 2; mi++)
#pragma unroll
                for (int j = 0; j < 4; j++) {
                    unsigned long long ap = pk2(av[mi][j], av[mi][j]);
                    acc[mi][j][0][0] = ffma2(ap, b0.x, acc[mi][j][0][0]);
                    acc[mi][j][0][1] = ffma2(ap, b0.y, acc[mi][j][0][1]);
                    acc[mi][j][1][0] = ffma2(ap, b1.x, acc[mi][j][1][0]);
                    acc[mi][j][1][1] = ffma2(ap, b1.y, acc[mi][j][1][1]);
                }
        }
        __syncthreads();
    }
    ulonglong2 bp0 = *(const ulonglong2*)&bias[tx * 4];
    ulonglong2 bp1 = *(const ulonglong2*)&bias[64 + tx * 4];
#pragma unroll
    for (int mi = 0; mi < 2; mi++)
#pragma unroll
        for (int j = 0; j < 4; j++) {
            int row = row0 + mi * 64 + ty * 4 + j;
            if (row < M) {
                ulonglong2 o0, o1;
                if (g_rowstart[row + 1] == g_rowstart[row]) {
                    o0 = *(const ulonglong2*)&g_hn[(size_t)row * 128 + tx * 4];
                    o1 = *(const ulonglong2*)&g_hn[(size_t)row * 128 + 64 + tx * 4];
                } else {
                    o0.x = fadd2(acc[mi][j][0][0], bp0.x);
                    o0.y = fadd2(acc[mi][j][0][1], bp0.y);
                    o1.x = fadd2(acc[mi][j][1][0], bp1.x);
                    o1.y = fadd2(acc[mi][j][1][1], bp1.y);
                }
                *(ulonglong2*)&C[(size_t)row * 128 + tx * 4] = o0;
                *(ulonglong2*)&C[(size_t)row * 128 + 64 + tx * 4] = o1;
            }
        }
}

// ---------------- fuse_gemm_v2: merged k_embed + fuse -----------------------
// From w tile: y = w@C3 (128 wide) and ow = w@Wee (32 wide, same As operands).
// s = sum lrelu(ow)*Wsf per edge (16-lane shfl reduce).
// z = s*y + P1[s]+P2[d]+b; att = lrelu(z)@W_attn; aw = att*s.
// Writes: g_ow, sat[:,256:288]=s*ow, sat[:,0:256]=hn gathers, g_logits, g_aw.
__global__ __launch_bounds__(256, 2)
void fuse_gemm_v2(const float* __restrict__ w,
                  const int* __restrict__ src, const int* __restrict__ dst,
                  const float* __restrict__ Wee, const float* __restrict__ Wsf,
                  const float* __restrict__ bif, const float* __restrict__ Wattn,
                  float* __restrict__ sat_out, int E) {
    __shared__ float As[32][132];
    __shared__ float Bs[32][132];
    __shared__ float Bse[32][36];
    __shared__ float sWsf[32];
    __shared__ float part[128][17];
    __shared__ float ss[128];
    int tid = threadIdx.x;
    int tx = tid & 15;
    int ty = tid >> 4;
    int row0 = blockIdx.x * 128;

    unsigned long long acc[2][4][2][2];
    unsigned long long oacc[2][4];
#pragma unroll
    for (int a = 0; a < 2; a++)
#pragma unroll
        for (int b = 0; b < 4; b++) {
            oacc[a][b] = 0ull;
#pragma unroll
            for (int c = 0; c < 2; c++)
#pragma unroll
                for (int d = 0; d < 2; d++) acc[a][b][c][d] = 0ull;
        }

    // load As = w tile (transposed)
#pragma unroll
    for (int i = 0; i < 4; i++) {
        int e = tid + 256 * i;
        int r = e >> 3;
        int kg = e & 7;
        float4 v = make_float4(0.f, 0.f, 0.f, 0.f);
        if (row0 + r < E)
            v = *(const float4*)&w[(size_t)(row0 + r) * 32 + kg * 4];
        As[kg * 4 + 0][r] = v.x;
        As[kg * 4 + 1][r] = v.y;
        As[kg * 4 + 2][r] = v.z;
        As[kg * 4 + 3][r] = v.w;
    }
    // load Bs = C3, Bse = Wee, sWsf
#pragma unroll
    for (int i = 0; i < 4; i++) {
        int e = tid + 256 * i;
        int k = e >> 5;
        int cg = e & 31;
        *(float4*)&Bs[k][cg * 4] = *(const float4*)&g_C3[k * 128 + cg * 4];
    }
    {
        int k = tid >> 3, c4 = tid & 7;
        *(float4*)&Bse[k][c4 * 4] = *(const float4*)&Wee[k * 32 + c4 * 4];
    }
    if (tid < 32) sWsf[tid] = Wsf[tid];
    __syncthreads();

#pragma unroll
    for (int k = 0; k < 32; k++) {
        float4 af0 = *(const float4*)&As[k][ty * 4];
        float4 af1 = *(const float4*)&As[k][64 + ty * 4];
        ulonglong2 b0 = *(const ulonglong2*)&Bs[k][tx * 4];
        ulonglong2 b1 = *(const ulonglong2*)&Bs[k][64 + tx * 4];
        unsigned long long be = *(const unsigned long long*)&Bse[k][tx * 2];
        float av[2][4] = {{af0.x, af0.y, af0.z, af0.w}, {af1.x, af1.y, af1.z, af1.w}};
#pragma unroll
        for (int mi = 0; mi < 2; mi++)
#pragma unroll
            for (int j = 0; j < 4; j++) {
                unsigned long long ap = pk2(av[mi][j], av[mi][j]);
                acc[mi][j][0][0] = ffma2(ap, b0.x, acc[mi][j][0][0]);
                acc[mi][j][0][1] = ffma2(ap, b0.y, acc[mi][j][0][1]);
                acc[mi][j][1][0] = ffma2(ap, b1.x, acc[mi][j][1][0]);
                acc[mi][j][1][1] = ffma2(ap, b1.y, acc[mi][j][1][1]);
                oacc[mi][j]      = ffma2(ap, be,  oacc[mi][j]);
            }
    }
    __syncthreads();

    float sfl = sWsf[tx * 2], sfh = sWsf[tx * 2 + 1];
    float4 bf0 = *(const float4*)&bif[tx * 4];
    float4 bf1 = *(const float4*)&bif[64 + tx * 4];
    float4 wa0 = *(const float4*)&Wattn[tx * 4];
    float4 wa1 = *(const float4*)&Wattn[64 + tx * 4];

#pragma unroll
    for (int mi = 0; mi < 2; mi++)
#pragma unroll
        for (int j = 0; j < 4; j++) {
            int rl = mi * 64 + ty * 4 + j;
            int row = row0 + rl;
            // ---- s for this row ----
            float olo, ohi;
            upk2(olo, ohi, oacc[mi][j]);
            float llo = olo > 0.f ? olo : 0.1f * olo;
            float lhi = ohi > 0.f ? ohi : 0.1f * ohi;
            float ps = fmaf(llo, sfl, lhi * sfh);
            ps += __shfl_xor_sync(0xffffffffu, ps, 1);
            ps += __shfl_xor_sync(0xffffffffu, ps, 2);
            ps += __shfl_xor_sync(0xffffffffu, ps, 4);
            ps += __shfl_xor_sync(0xffffffffu, ps, 8);
            float sE = ps;   // s for edge `row`, identical in all 16 tx lanes
            if (tx == 0) ss[rl] = sE;

            float partial = 0.f;
            if (row < E) {
                // ow / s*ow outputs (2 floats per lane = 32 cols)
                float2 owv = make_float2(olo, ohi);
                *(float2*)&g_ow[(size_t)row * 32 + tx * 2] = owv;
                float2 sow = make_float2(sE * olo, sE * ohi);
                *(float2*)&sat_out[(size_t)row * 288 + 256 + tx * 2] = sow;

                int s = src[row], d = dst[row];
                float4 p1a = *(const float4*)&g_P1[(size_t)s * 128 + tx * 4];
                float4 p2a = *(const float4*)&g_P2[(size_t)d * 128 + tx * 4];
                float4 p1b = *(const float4*)&g_P1[(size_t)s * 128 + 64 + tx * 4];
                float4 p2b = *(const float4*)&g_P2[(size_t)d * 128 + 64 + tx * 4];
                float z[8];
                upk2(z[0], z[1], acc[mi][j][0][0]);
                upk2(z[2], z[3], acc[mi][j][0][1]);
                upk2(z[4], z[5], acc[mi][j][1][0]);
                upk2(z[6], z[7], acc[mi][j][1][1]);
                z[0] = fmaf(sE, z[0], p1a.x + p2a.x + bf0.x);
                z[1] = fmaf(sE, z[1], p1a.y + p2a.y + bf0.y);
                z[2] = fmaf(sE, z[2], p1a.z + p2a.z + bf0.z);
                z[3] = fmaf(sE, z[3], p1a.w + p2a.w + bf0.w);
                z[4] = fmaf(sE, z[4], p1b.x + p2b.x + bf1.x);
                z[5] = fmaf(sE, z[5], p1b.y + p2b.y + bf1.y);
                z[6] = fmaf(sE, z[6], p1b.z + p2b.z + bf1.z);
                z[7] = fmaf(sE, z[7], p1b.w + p2b.w + bf1.w);
                float wv[8] = {wa0.x, wa0.y, wa0.z, wa0.w, wa1.x, wa1.y, wa1.z, wa1.w};
#pragma unroll
                for (int c = 0; c < 8; c++) {
                    float l = z[c] > 0.f ? z[c] : 0.1f * z[c];
                    partial = fmaf(l, wv[c], partial);
                }
                size_t so = (size_t)row * 288;
                *(float4*)&sat_out[so + tx * 4]        = *(const float4*)&g_hn[(size_t)s * 128 + tx * 4];
                *(float4*)&sat_out[so + 64 + tx * 4]   = *(const float4*)&g_hn[(size_t)s * 128 + 64 + tx * 4];
                *(float4*)&sat_out[so + 128 + tx * 4]  = *(const float4*)&g_hn[(size_t)d * 128 + tx * 4];
                *(float4*)&sat_out[so + 192 + tx * 4]  = *(const float4*)&g_hn[(size_t)d * 128 + 64 + tx * 4];
            }
            part[rl][tx] = partial;
        }
    __syncthreads();
    if (tid < 128) {
        int row = row0 + tid;
        if (row < E) {
            float v = 0.f;
#pragma unroll
            for (int i = 0; i < 16; i++) v += part[tid][i];
            g_logits[row] = v;
            g_aw[row] = v * ss[tid];
        }
    }
}

// ---------------- segment softmax + aggregate + hn copy (warp per node) -----
__global__ void segment_kernel(const int* __restrict__ src, int Nn) {
    int warp = (blockIdx.x * blockDim.x + threadIdx.x) >> 5;
    int lane = threadIdx.x & 31;
    if (warp >= Nn) return;
    int s0 = g_rowstart[warp], s1 = g_rowstart[warp + 1];
    float acc[5] = {0.f, 0.f, 0.f, 0.f, 0.f};
    if (s1 > s0) {
        float m = -INFINITY;
        for (int e = s0 + lane; e < s1; e += 32) m = fmaxf(m, g_logits[e]);
#pragma unroll
        for (int o = 16; o; o >>= 1) m = fmaxf(m, __shfl_xor_sync(0xffffffffu, m, o));
        float den = 0.f;
        for (int e = s0 + lane; e < s1; e += 32) den += expf(g_logits[e] - m);
#pragma unroll
        for (int o = 16; o; o >>= 1) den += __shfl_xor_sync(0xffffffffu, den, o);
        float inv = 1.0f / den;
        for (int e = s0; e < s1; e++) {
            float alpha = expf(g_logits[e] - m) * inv;
            int sidx = src[e];
#pragma unroll
            for (int i = 0; i < 4; i++)
                acc[i] = fmaf(alpha, g_hn[(size_t)sidx * 128 + lane + 32 * i], acc[i]);
            acc[4] = fmaf(alpha * g_aw[e], g_ow[(size_t)e * 32 + lane], acc[4]);
        }
    }
#pragma unroll
    for (int i = 0; i < 4; i++) g_Acat[(size_t)warp * 288 + lane + 32 * i] = acc[i];
    g_Acat[(size_t)warp * 288 + 128 + lane] = acc[4];
    float4 hv = *(const float4*)&g_hn[(size_t)warp * 128 + lane * 4];
    *(float4*)&g_Acat[(size_t)warp * 288 + 160 + lane * 4] = hv;
}

// ---------------- wout_gemm: wout = w@C2 + aw*(w@C1) + Q1[s]+Q2[d]+cvec -----
__global__ __launch_bounds__(256, 2)
void wout_gemm(const float* __restrict__ w, const int* __restrict__ src,
               const int* __restrict__ dst, float* __restrict__ wout, int E) {
    __shared__ float As[32][132];
    __shared__ float Bs[32][132];
    __shared__ float saw[128];
    int tid = threadIdx.x;
    int tx = tid & 15;
    int ty = tid >> 4;
    int row0 = blockIdx.x * 128;

    if (tid < 128) saw[tid] = (row0 + tid < E) ? g_aw[row0 + tid] : 0.f;

    unsigned long long acc[2][4][2][2];
#pragma unroll
    for (int a = 0; a < 2; a++)
#pragma unroll
        for (int b = 0; b < 4; b++)
#pragma unroll
            for (int c = 0; c < 2; c++)
#pragma unroll
                for (int d = 0; d < 2; d++) acc[a][b][c][d] = 0ull;

#pragma unroll
    for (int chunk = 0; chunk < 2; chunk++) {
        const float* Bsrc = chunk == 0 ? g_C2 : g_C1;
        if (chunk) __syncthreads();
#pragma unroll
        for (int i = 0; i < 4; i++) {
            int e = tid + 256 * i;
            int r = e >> 3;
            int kg = e & 7;
            float4 v = make_float4(0.f, 0.f, 0.f, 0.f);
            if (row0 + r < E)
                v = *(const float4*)&w[(size_t)(row0 + r) * 32 + kg * 4];
            float sc = chunk == 0 ? 1.f : saw[r];
            As[kg * 4 + 0][r] = sc * v.x;
            As[kg * 4 + 1][r] = sc * v.y;
            As[kg * 4 + 2][r] = sc * v.z;
            As[kg * 4 + 3][r] = sc * v.w;
        }
#pragma unroll
        for (int i = 0; i < 4; i++) {
            int e = tid + 256 * i;
            int k = e >> 5;
            int cg = e & 31;
            *(float4*)&Bs[k][cg * 4] = *(const float4*)&Bsrc[k * 128 + cg * 4];
        }
        __syncthreads();
#pragma unroll
        for (int k = 0; k < 32; k++) {
            float4 af0 = *(const float4*)&As[k][ty * 4];
            float4 af1 = *(const float4*)&As[k][64 + ty * 4];
            ulonglong2 b0 = *(const ulonglong2*)&Bs[k][tx * 4];
            ulonglong2 b1 = *(const ulonglong2*)&Bs[k][64 + tx * 4];
            float av[2][4] = {{af0.x, af0.y, af0.z, af0.w}, {af1.x, af1.y, af1.z, af1.w}};
#pragma unroll
            for (int mi = 0; mi < 2; mi++)
#pragma unroll
                for (int j = 0; j < 4; j++) {
                    unsigned long long ap = pk2(av[mi][j], av[mi][j]);
                    acc[mi][j][0][0] = ffma2(ap, b0.x, acc[mi][j][0][0]);
                    acc[mi][j][0][1] = ffma2(ap, b0.y, acc[mi][j][0][1]);
                    acc[mi][j][1][0] = ffma2(ap, b1.x, acc[mi][j][1][0]);
                    acc[mi][j][1][1] = ffma2(ap, b1.y, acc[mi][j][1][1]);
                }
        }
    }
    float4 cv0 = *(const float4*)&g_cvec[tx * 4];
    float4 cv1 = *(const float4*)&g_cvec[64 + tx * 4];
#pragma unroll
    for (int mi = 0; mi < 2; mi++)
#pragma unroll
        for (int j = 0; j < 4; j++) {
            int row = row0 + mi * 64 + ty * 4 + j;
            if (row < E) {
                int s = src[row], d = dst[row];
                float4 q1a = *(const float4*)&g_Q1[(size_t)s * 128 + tx * 4];
                float4 q2a = *(const float4*)&g_Q2[(size_t)d * 128 + tx * 4];
                float4 q1b = *(const float4*)&g_Q1[(size_t)s * 128 + 64 + tx * 4];
                float4 q2b = *(const float4*)&g_Q2[(size_t)d * 128 + 64 + tx * 4];
                float z[8];
                upk2(z[0], z[1], acc[mi][j][0][0]);
                upk2(z[2], z[3], acc[mi][j][0][1]);
                upk2(z[4], z[5], acc[mi][j][1][0]);
                upk2(z[6], z[7], acc[mi][j][1][1]);
                float4 o0, o1;
                o0.x = z[0] + q1a.x + q2a.x + cv0.x;
                o0.y = z[1] + q1a.y + q2a.y + cv0.y;
                o0.z = z[2] + q1a.z + q2a.z + cv0.z;
                o0.w = z[3] + q1a.w + q2a.w + cv0.w;
                o1.x = z[4] + q1b.x + q2b.x + cv1.x;
                o1.y = z[5] + q1b.y + q2b.y + cv1.y;
                o1.z = z[6] + q1b.z + q2b.z + cv1.z;
                o1.w = z[7] + q1b.w + q2b.w + cv1.w;
                *(float4*)&wout[(size_t)row * 128 + tx * 4] = o0;
                *(float4*)&wout[(size_t)row * 128 + 64 + tx * 4] = o1;
            }
        }
}

// ---------------- launch ----------------
extern "C" void kernel_launch(void* const* d_in, const int* in_sizes, int n_in,
                              void* d_out, int out_size) {
    const float* h        = (const float*)d_in[0];
    const float* w        = (const float*)d_in[1];
    const int*   src      = (const int*)d_in[2];
    const int*   dst      = (const int*)d_in[3];
    const float* W_en     = (const float*)d_in[4];
    const float* W_attn   = (const float*)d_in[5];
    const float* W_if     = (const float*)d_in[6];
    const float* b_if     = (const float*)d_in[7];
    const float* W_ee     = (const float*)d_in[8];
    const float* W_sf     = (const float*)d_in[9];
    const float* W_conc   = (const float*)d_in[10];
    const float* b_conc   = (const float*)d_in[11];
    const float* bn_gamma = (const float*)d_in[12];
    const float* bn_beta  = (const float*)d_in[13];
    const float* bn_mean  = (const float*)d_in[14];
    const float* bn_var   = (const float*)d_in[15];
    const float* W_ag     = (const float*)d_in[16];

    int Nn = in_sizes[0] / 128;
    int E  = in_sizes[2];

    float* out_hnew = (float*)d_out;
    float* out_wout = out_hnew + (size_t)Nn * 128;
    float* out_sat  = out_wout + (size_t)E * 128;

    float *hn_p, *P1_p, *P2_p, *Q1_p, *Q2_p, *Acat_p;
    cudaGetSymbolAddress((void**)&hn_p,   g_hn);
    cudaGetSymbolAddress((void**)&P1_p,   g_P1);
    cudaGetSymbolAddress((void**)&P2_p,   g_P2);
    cudaGetSymbolAddress((void**)&Q1_p,   g_Q1);
    cudaGetSymbolAddress((void**)&Q2_p,   g_Q2);
    cudaGetSymbolAddress((void**)&Acat_p, g_Acat);

    int gbN = (Nn + 127) / 128;
    int gbE = (E + 127) / 128;

    rowstart_kernel<<<(Nn + 256) / 256, 256>>>(dst, E, Nn);
    prep_cmat<<<1, 128>>>(W_if + 256 * 128, W_ag + 256 * 128, W_ee,
                          bn_gamma, bn_beta, bn_mean, bn_var);
    gemm_v3<<<gbN, 256>>>(h, W_en, nullptr, hn_p, Nn, 128);
    gemm_v3<<<gbN, 256>>>(hn_p, W_if,             nullptr, P1_p, Nn, 128);
    gemm_v3<<<gbN, 256>>>(hn_p, W_if + 128 * 128, nullptr, P2_p, Nn, 128);
    fuse_gemm_v2<<<gbE, 256>>>(w, src, dst, W_ee, W_sf, b_if, W_attn, out_sat, E);
    segment_kernel<<<(Nn + 7) / 8, 256>>>(src, Nn);
    gemm_conc<<<gbN, 256>>>(Acat_p, W_conc, b_conc, out_hnew, Nn, 288);
    gemm_v3<<<gbN, 256>>>(out_hnew, W_ag,             nullptr, Q1_p, Nn, 128);
    gemm_v3<<<gbN, 256>>>(out_hnew, W_ag + 128 * 128, nullptr, Q2_p, Nn, 128);
    wout_gemm<<<gbE, 256>>>(w, src, dst, out_wout, E);
}